// round 2
// baseline (speedup 1.0000x reference)
#include <cuda_runtime.h>
#include <math.h>

// ---------------- problem constants (fixed shapes) ---------------------------
#define NTH   512
#define T_LEN 128
#define OBS   32
#define CC    33      // obs + 1 (time channel)
#define HID   64
#define WID   128
#define FOUT  2112    // HID * CC
#define NQ    528     // FOUT / 4

#define ACT_NONE 0
#define ACT_RELU 1
#define ACT_SP   2

// ---------------- device scratch: transposed (k-major) weights ---------------
__device__ __align__(16) float g_fWoT[WID * FOUT];     // [k][o]
__device__ __align__(16) float g_fWhT[3 * WID * WID];  // [l][k][o]
__device__ __align__(16) float g_iWhT[3 * WID * WID];
__device__ __align__(16) float g_fW0T[HID * WID];      // [k<64][o<128]
__device__ __align__(16) float g_iW0T[CC * WID];       // [k<33][o<128]
__device__ __align__(16) float g_iWoT[WID * HID];      // [k<128][o<64]
__device__ __align__(16) float g_lWT [HID * OBS];      // [k<64][o<32]

__global__ void prep_transpose(const float* __restrict__ iW0, const float* __restrict__ iWh,
                               const float* __restrict__ iWo, const float* __restrict__ fW0,
                               const float* __restrict__ fWh, const float* __restrict__ fWo,
                               const float* __restrict__ lW) {
    int idx = blockIdx.x * blockDim.x + threadIdx.x;
    int str = gridDim.x * blockDim.x;
    for (int i = idx; i < FOUT * WID; i += str) {           // fWo (2112,128)
        int o = i >> 7, k = i & 127;
        g_fWoT[k * FOUT + o] = fWo[i];
    }
    for (int i = idx; i < 3 * WID * WID; i += str) {        // fWh / iWh (3,128,128)
        int l = i >> 14, rem = i & 16383, o = rem >> 7, k = rem & 127;
        g_fWhT[(l << 14) + k * WID + o] = fWh[i];
        g_iWhT[(l << 14) + k * WID + o] = iWh[i];
    }
    for (int i = idx; i < WID * HID; i += str) {            // fW0 (128,64) row-major
        int o = i >> 6, k = i & 63;
        g_fW0T[k * WID + o] = fW0[i];
    }
    for (int i = idx; i < WID * CC; i += str) {             // iW0 (128,33)
        int o = i / CC, k = i - o * CC;
        g_iW0T[k * WID + o] = iW0[i];
    }
    for (int i = idx; i < HID * WID; i += str) {            // iWo (64,128)
        int o = i >> 7, k = i & 127;
        g_iWoT[k * HID + o] = iWo[i];
    }
    for (int i = idx; i < OBS * HID; i += str) {            // lW (32,64)
        int o = i >> 6, k = i & 63;
        g_lWT[k * OBS + o] = lW[i];
    }
}

// stable softplus matching jax.nn.softplus numerics
__device__ __forceinline__ float softplus_f(float x) {
    return fmaxf(x, 0.f) + log1pf(expf(-fabsf(x)));
}

// cooperative matvec: out[o] = act( sum_k WT[k*O + o] * x[k] + bias[o] )
template <int O, int PARTS, int ACT>
__device__ __forceinline__ void mv(const float* __restrict__ WT, int I,
                                   const float* __restrict__ x,
                                   const float* __restrict__ bias,
                                   float* __restrict__ outv,
                                   float* __restrict__ s_part) {
    const int tid = threadIdx.x;
    const int r = tid & (O - 1);
    const int p = tid / O;
    float acc = 0.f;
#pragma unroll 4
    for (int k = p; k < I; k += PARTS)
        acc = fmaf(WT[k * O + r], x[k], acc);
    s_part[tid] = acc;
    __syncthreads();
    if (tid < O) {
        float v = bias[tid];
#pragma unroll
        for (int j = 0; j < PARTS; j++) v += s_part[tid + j * O];
        if (ACT == ACT_RELU) v = fmaxf(v, 0.f);
        if (ACT == ACT_SP)   v = softplus_f(v);
        outv[tid] = v;
    }
    __syncthreads();
}

__global__ void __launch_bounds__(NTH, 1)
ncde_main(const float* __restrict__ ts, const float* __restrict__ ys,
          const float* __restrict__ ib0, const float* __restrict__ ibh,
          const float* __restrict__ ibo, const float* __restrict__ fb0,
          const float* __restrict__ fbh, const float* __restrict__ fbo,
          const float* __restrict__ lb, float* __restrict__ out) {
    extern __shared__ float sm[];
    float* s_fWhT = sm;                      // 49152
    float* s_tys  = s_fWhT + 3 * WID * WID;  // 4224  (T x 33)
    float* s_P    = s_tys + T_LEN * CC;      // 2112  (tanh outputs)
    float* s_part = s_P + FOUT;              // 512
    float* s_ha   = s_part + NTH;            // 128
    float* s_hb   = s_ha + WID;              // 128
    float* s_fb0  = s_hb + WID;              // 128
    float* s_fbh  = s_fb0 + WID;             // 384
    float* s_y    = s_fbh + 3 * WID;         // 64
    float* s_yt   = s_y + HID;               // 64
    float* s_ks   = s_yt + HID;              // 64
    float* s_f    = s_ks + HID;              // 64
    float* s_xd   = s_f + HID;               // 36
    float* s_d0   = s_xd + 36;               // 36
    float* s_cc   = s_d0 + 36;               // 36
    float* s_bb   = s_cc + 36;               // 36
    float* s_in   = s_bb + 36;               // 36
    float* s_o32  = s_in + 36;               // 32

    const int tid = threadIdx.x;
    const int b = blockIdx.x;

    // --- stage fWhT into shared; build tys; cache biases ---------------------
    {
        const float4* src = (const float4*)g_fWhT;
        float4* dst = (float4*)s_fWhT;
        for (int i = tid; i < 3 * WID * WID / 4; i += NTH) dst[i] = src[i];
    }
    for (int i = tid; i < T_LEN * CC; i += NTH) {
        int t = i / CC, c = i - t * CC;
        s_tys[i] = (c == 0) ? ts[t] : ys[(b * T_LEN + t) * OBS + (c - 1)];
    }
    if (tid < WID)     s_fb0[tid] = fb0[tid];
    if (tid < 3 * WID) s_fbh[tid] = fbh[tid];
    __syncthreads();

    // --- initial MLP (relu hidden, identity out) -> y0 -----------------------
    if (tid < CC) s_in[tid] = s_tys[tid];
    __syncthreads();
    mv<WID, 4, ACT_RELU>(g_iW0T, CC, s_in, ib0, s_ha, s_part);
    mv<WID, 4, ACT_RELU>(g_iWhT,          WID, s_ha, ibh,           s_hb, s_part);
    mv<WID, 4, ACT_RELU>(g_iWhT + 16384,  WID, s_hb, ibh + WID,     s_ha, s_part);
    mv<WID, 4, ACT_RELU>(g_iWhT + 32768,  WID, s_ha, ibh + 2 * WID, s_hb, s_part);
    mv<HID, 8, ACT_NONE>(g_iWoT, WID, s_hb, ibo, s_y, s_part);

    // readout t = 0
    mv<OBS, 16, ACT_NONE>(g_lWT, HID, s_y, lb, s_o32, s_part);
    if (tid < OBS) out[(b * T_LEN + 0) * OBS + tid] = s_o32[tid];

    // --- vector field: s_f = tanh-MLP(yy).reshape(64,33) @ xdot(s) -----------
    auto vf = [&](float s, const float* yy) {
        if (tid < CC) {
            s_xd[tid] = s_d0[tid] + 2.f * s_cc[tid] * s + 3.f * s_bb[tid] * s * s;
        }
        mv<WID, 4, ACT_SP>(g_fW0T, HID, yy, s_fb0, s_ha, s_part);
        mv<WID, 4, ACT_SP>(s_fWhT,         WID, s_ha, s_fbh,           s_hb, s_part);
        mv<WID, 4, ACT_SP>(s_fWhT + 16384, WID, s_hb, s_fbh + WID,     s_ha, s_part);
        mv<WID, 4, ACT_SP>(s_fWhT + 32768, WID, s_ha, s_fbh + 2 * WID, s_hb, s_part);
        // wide output layer streamed from L2 (coalesced float4)
        {
            const float4* W4 = (const float4*)g_fWoT;  // [k][NQ] float4 columns
            const float4* b4 = (const float4*)fbo;
            for (int q = tid; q < NQ; q += NTH) {
                float4 a = b4[q];
                const float4* wp = W4 + q;
#pragma unroll 4
                for (int k = 0; k < WID; k++) {
                    float4 w = *wp; wp += NQ;
                    float xk = s_hb[k];
                    a.x = fmaf(w.x, xk, a.x);
                    a.y = fmaf(w.y, xk, a.y);
                    a.z = fmaf(w.z, xk, a.z);
                    a.w = fmaf(w.w, xk, a.w);
                }
                float4 t4;
                t4.x = tanhf(a.x); t4.y = tanhf(a.y);
                t4.z = tanhf(a.z); t4.w = tanhf(a.w);
                ((float4*)s_P)[q] = t4;
            }
            __syncthreads();
        }
        // contraction over C=33 channels
        if (tid < HID) {
            float a = 0.f;
            const float* pr = s_P + tid * CC;
#pragma unroll
            for (int c = 0; c < CC; c++) a = fmaf(pr[c], s_xd[c], a);
            s_f[tid] = a;
        }
        __syncthreads();
    };

    // --- interval scan + RK4 (NSUB = 4) --------------------------------------
    for (int iv = 0; iv < T_LEN - 1; iv++) {
        float dti = s_tys[(iv + 1) * CC] - s_tys[iv * CC];
        if (tid < CC) {
            float di = (s_tys[(iv + 1) * CC + tid] - s_tys[iv * CC + tid]) / dti;
            float d0v;
            if (iv == 0) {
                d0v = di;
            } else {
                float dtm = s_tys[iv * CC] - s_tys[(iv - 1) * CC];
                d0v = (s_tys[iv * CC + tid] - s_tys[(iv - 1) * CC + tid]) / dtm;
            }
            float d1v = di;
            s_d0[tid] = d0v;
            s_cc[tid] = (3.f * di - 2.f * d0v - d1v) / dti;
            s_bb[tid] = (d0v + d1v - 2.f * di) / (dti * dti);
        }
        __syncthreads();

        float hsub = dti * 0.25f;
#pragma unroll 1
        for (int sub = 0; sub < 4; sub++) {
            float s0 = hsub * (float)sub;
            vf(s0, s_y);
            if (tid < HID) {
                float k1 = s_f[tid];
                s_ks[tid] = k1;
                s_yt[tid] = fmaf(0.5f * hsub, k1, s_y[tid]);
            }
            __syncthreads();
            vf(s0 + 0.5f * hsub, s_yt);
            if (tid < HID) {
                float k2 = s_f[tid];
                s_ks[tid] += 2.f * k2;
                s_yt[tid] = fmaf(0.5f * hsub, k2, s_y[tid]);
            }
            __syncthreads();
            vf(s0 + 0.5f * hsub, s_yt);
            if (tid < HID) {
                float k3 = s_f[tid];
                s_ks[tid] += 2.f * k3;
                s_yt[tid] = fmaf(hsub, k3, s_y[tid]);
            }
            __syncthreads();
            vf(s0 + hsub, s_yt);
            if (tid < HID) {
                s_y[tid] = fmaf(hsub * (1.f / 6.f), s_ks[tid] + s_f[tid], s_y[tid]);
            }
            __syncthreads();
        }

        // readout t = iv + 1
        mv<OBS, 16, ACT_NONE>(g_lWT, HID, s_y, lb, s_o32, s_part);
        if (tid < OBS) out[(b * T_LEN + iv + 1) * OBS + tid] = s_o32[tid];
    }
}

// ---------------- launch ------------------------------------------------------
static const int SMEM_BYTES = (3 * WID * WID + T_LEN * CC + FOUT + NTH + 3 * WID
                               + 3 * WID + 4 * HID + 5 * 36 + 32) * (int)sizeof(float);

extern "C" void kernel_launch(void* const* d_in, const int* in_sizes, int n_in,
                              void* d_out, int out_size) {
    const float* ts  = (const float*)d_in[0];
    const float* ys  = (const float*)d_in[1];
    const float* iW0 = (const float*)d_in[2];
    const float* ib0 = (const float*)d_in[3];
    const float* iWh = (const float*)d_in[4];
    const float* ibh = (const float*)d_in[5];
    const float* iWo = (const float*)d_in[6];
    const float* ibo = (const float*)d_in[7];
    const float* fW0 = (const float*)d_in[8];
    const float* fb0 = (const float*)d_in[9];
    const float* fWh = (const float*)d_in[10];
    const float* fbh = (const float*)d_in[11];
    const float* fWo = (const float*)d_in[12];
    const float* fbo = (const float*)d_in[13];
    const float* lW  = (const float*)d_in[14];
    const float* lb  = (const float*)d_in[15];
    float* out = (float*)d_out;

    cudaFuncSetAttribute(ncde_main, cudaFuncAttributeMaxDynamicSharedMemorySize, SMEM_BYTES);

    prep_transpose<<<96, 256>>>(iW0, iWh, iWo, fW0, fWh, fWo, lW);
    ncde_main<<<64, NTH, SMEM_BYTES>>>(ts, ys, ib0, ibh, ibo, fb0, fbh, fbo, lb, out);
}

// round 3
// speedup vs baseline: 1.4417x; 1.4417x over previous
#include <cuda_runtime.h>
#include <cuda_fp16.h>
#include <math.h>

// ---------------- problem constants (fixed shapes) ---------------------------
#define NTH   512
#define T_LEN 128
#define OBS   32
#define CC    33      // obs + 1 (time channel)
#define HID   64
#define WID   128
#define FOUT  2112    // HID * CC

#define ACT_NONE 0
#define ACT_RELU 1
#define ACT_SP   2

// fWo in fp16, warp-interleaved chunk layout:
// chunk index = w*2112 + i*32 + lane   (chunk = 8 halves = 16B)
// thread tid: w = tid>>5, lane = tid&31, h = tid>>3, p = tid&7
// half j of chunk i belongs to e = i*8+j, c = e%33, kk = e/33:
//   weight = fWo[(h*33 + c)*128 + (p*16 + kk)]
__device__ __align__(16) __half g_fWoH[FOUT * WID];   // 540,672 B

__global__ void prep_fwo(const float* __restrict__ fWo) {
    int chunk = blockIdx.x * blockDim.x + threadIdx.x;   // 33792 chunks
    if (chunk >= (FOUT * WID) / 8) return;
    int w = chunk / 2112;
    int rem = chunk - w * 2112;
    int i = rem >> 5;
    int lane = rem & 31;
    int h = w * 4 + (lane >> 3);
    int p = lane & 7;
#pragma unroll
    for (int j = 0; j < 8; j++) {
        int e = i * 8 + j;
        int c = e % 33, kk = e / 33;
        float v = fWo[(h * 33 + c) * WID + (p * 16 + kk)];
        g_fWoH[chunk * 8 + j] = __float2half(v);
    }
}

// stable softplus matching jax.nn.softplus
__device__ __forceinline__ float softplus_f(float x) {
    return fmaxf(x, 0.f) + log1pf(expf(-fabsf(x)));
}

// warp-cooperative matvec: 16 warps, warp w computes outputs [w*OPW, w*OPW+OPW).
// W row-major [O][I]. One barrier needed AFTER the call (caller's duty).
template <int OPW, int I, int ACT>
__device__ __forceinline__ void mvw(const float* __restrict__ W,
                                    const float* __restrict__ x,
                                    const float* __restrict__ bias,
                                    float* __restrict__ outv) {
    constexpr int NJ = (I + 31) / 32;
    const int w = threadIdx.x >> 5;
    const int l = threadIdx.x & 31;
    float xr[NJ];
#pragma unroll
    for (int j = 0; j < NJ; j++) {
        int k = l + 32 * j;
        xr[j] = (k < I) ? x[k] : 0.f;
    }
    float acc[OPW];
#pragma unroll
    for (int oo = 0; oo < OPW; oo++) {
        const float* row = W + (w * OPW + oo) * I;
        float a = 0.f;
#pragma unroll
        for (int j = 0; j < NJ; j++) {
            int k = l + 32 * j;
            if (k < I) a = fmaf(row[k], xr[j], a);
        }
        acc[oo] = a;
    }
#pragma unroll
    for (int d = 16; d >= 1; d >>= 1)
#pragma unroll
        for (int oo = 0; oo < OPW; oo++)
            acc[oo] += __shfl_xor_sync(0xFFFFFFFFu, acc[oo], d);
    if (l < OPW) {
        float v = acc[l] + bias[w * OPW + l];
        if (ACT == ACT_RELU) v = fmaxf(v, 0.f);
        if (ACT == ACT_SP)   v = softplus_f(v);
        outv[w * OPW + l] = v;
    }
}

__global__ void __launch_bounds__(NTH, 1)
ncde_main(const float* __restrict__ ts, const float* __restrict__ ys,
          const float* __restrict__ iW0, const float* __restrict__ ib0,
          const float* __restrict__ iWh, const float* __restrict__ ibh,
          const float* __restrict__ iWo, const float* __restrict__ ibo,
          const float* __restrict__ fW0, const float* __restrict__ fb0g,
          const float* __restrict__ fWh, const float* __restrict__ fbhg,
          const float* __restrict__ fbo, const float* __restrict__ lW,
          const float* __restrict__ lb, float* __restrict__ out) {
    extern __shared__ float sm[];
    float* s_fWh = sm;                       // 3*128*128 = 49152 floats
    float* s_tys = s_fWh + 3 * WID * WID;    // 128*33 = 4224
    float* s_fbo = s_tys + T_LEN * CC;       // 2112
    float* s_fb0 = s_fbo + FOUT;             // 128
    float* s_fbh = s_fb0 + WID;              // 384
    float* s_ha  = s_fbh + 3 * WID;          // 128
    float* s_hb  = s_ha + WID;               // 128
    float* s_y   = s_hb + WID;               // 64
    float* s_yt  = s_y + HID;                // 64
    float* s_ks  = s_yt + HID;               // 64
    float* s_f   = s_ks + HID;               // 64
    float* s_xd  = s_f + HID;                // 36
    float* s_d0  = s_xd + 36;                // 36
    float* s_cc  = s_d0 + 36;                // 36
    float* s_bb  = s_cc + 36;                // 36

    const int tid = threadIdx.x;
    const int b = blockIdx.x;
    const int p = tid & 7;         // k-eighth
    const int h = tid >> 3;        // hid row
    const int wrp = tid >> 5;
    const int lane = tid & 31;

    // --- stage fWh (row-major, no transpose) into shared; tys; biases --------
    {
        const float4* src = (const float4*)fWh;
        float4* dst = (float4*)s_fWh;
        for (int i = tid; i < 3 * WID * WID / 4; i += NTH) dst[i] = src[i];
    }
    for (int i = tid; i < T_LEN * CC; i += NTH) {
        int t = i / CC, c = i - t * CC;
        s_tys[i] = (c == 0) ? ts[t] : ys[(b * T_LEN + t) * OBS + (c - 1)];
    }
    for (int i = tid; i < FOUT; i += NTH) s_fbo[i] = fbo[i];
    if (tid < WID)     s_fb0[tid] = fb0g[tid];
    if (tid < 3 * WID) s_fbh[tid] = fbhg[tid];
    __syncthreads();

    // --- initial MLP (relu hidden, identity out) -> y0 -----------------------
    mvw<8, CC, ACT_RELU>(iW0, s_tys, ib0, s_ha);               __syncthreads();
    mvw<8, WID, ACT_RELU>(iWh,              s_ha, ibh,           s_hb); __syncthreads();
    mvw<8, WID, ACT_RELU>(iWh + 16384,      s_hb, ibh + WID,     s_ha); __syncthreads();
    mvw<8, WID, ACT_RELU>(iWh + 32768,      s_ha, ibh + 2 * WID, s_hb); __syncthreads();
    mvw<4, WID, ACT_NONE>(iWo, s_hb, ibo, s_y);                 __syncthreads();

    // readout t = 0
    mvw<2, HID, ACT_NONE>(lW, s_y, lb, out + (b * T_LEN + 0) * OBS);

    // --- vector field: s_f = tanh(fWo@hb + fbo).reshape(64,33) @ xd ----------
    auto vf = [&](float s, const float* __restrict__ yy) {
        if (tid < CC)
            s_xd[tid] = s_d0[tid] + 2.f * s_cc[tid] * s + 3.f * s_bb[tid] * s * s;
        mvw<8, HID, ACT_SP>(fW0, yy, s_fb0, s_ha);                       __syncthreads();
        mvw<8, WID, ACT_SP>(s_fWh,         s_ha, s_fbh,           s_hb); __syncthreads();
        mvw<8, WID, ACT_SP>(s_fWh + 16384, s_hb, s_fbh + WID,     s_ha); __syncthreads();
        mvw<8, WID, ACT_SP>(s_fWh + 32768, s_ha, s_fbh + 2 * WID, s_hb); __syncthreads();

        // ---- wide fp16 output layer, fused bias+tanh+contraction ----
        {
            const int k0 = p * 16;
            const uint4* P = ((const uint4*)g_fWoH) + (size_t)wrp * 2112 + lane;
            float z[33];
#pragma unroll
            for (int c = 0; c < 33; c++) z[c] = 0.f;
            for (int blk = 0; blk < 2; blk++) {
                int kb = k0 + 8 * blk;
#pragma unroll
                for (int ii = 0; ii < 33; ii++) {
                    uint4 r = P[(blk * 33 + ii) * 32];
                    const __half2* hh = (const __half2*)&r;
#pragma unroll
                    for (int q = 0; q < 4; q++) {
                        float2 f = __half22float2(hh[q]);
                        int e0 = ii * 8 + q * 2;
                        int e1 = e0 + 1;
                        z[e0 % 33] = fmaf(f.x, s_hb[kb + e0 / 33], z[e0 % 33]);
                        z[e1 % 33] = fmaf(f.y, s_hb[kb + e1 / 33], z[e1 % 33]);
                    }
                }
            }
            // reduce partial sums over the 8 k-eighths (lanes sharing h)
#pragma unroll
            for (int d = 1; d <= 4; d <<= 1)
#pragma unroll
                for (int c = 0; c < 33; c++)
                    z[c] += __shfl_xor_sync(0xFFFFFFFFu, z[c], d);
            // fused bias + tanh + channel contraction
            float part = 0.f;
#pragma unroll
            for (int m = 0; m < 5; m++) {
                int c = p + 8 * m;
                if (c < 33) {
                    float zc = z[c] + s_fbo[h * 33 + c];
                    part = fmaf(tanhf(zc), s_xd[c], part);
                }
            }
#pragma unroll
            for (int d = 1; d <= 4; d <<= 1)
                part += __shfl_xor_sync(0xFFFFFFFFu, part, d);
            if (p == 0) s_f[h] = part;
            __syncthreads();
        }
    };

    // --- interval scan + RK4 (NSUB = 4) --------------------------------------
    for (int iv = 0; iv < T_LEN - 1; iv++) {
        float dti = s_tys[(iv + 1) * CC] - s_tys[iv * CC];
        if (tid < CC) {
            float di = (s_tys[(iv + 1) * CC + tid] - s_tys[iv * CC + tid]) / dti;
            float d0v;
            if (iv == 0) {
                d0v = di;
            } else {
                float dtm = s_tys[iv * CC] - s_tys[(iv - 1) * CC];
                d0v = (s_tys[iv * CC + tid] - s_tys[(iv - 1) * CC + tid]) / dtm;
            }
            float d1v = di;
            s_d0[tid] = d0v;
            s_cc[tid] = (3.f * di - 2.f * d0v - d1v) / dti;
            s_bb[tid] = (d0v + d1v - 2.f * di) / (dti * dti);
        }
        __syncthreads();

        float hsub = dti * 0.25f;
#pragma unroll 1
        for (int sub = 0; sub < 4; sub++) {
            float s0 = hsub * (float)sub;
            vf(s0, s_y);
            if (tid < HID) {
                float k1 = s_f[tid];
                s_ks[tid] = k1;
                s_yt[tid] = fmaf(0.5f * hsub, k1, s_y[tid]);
            }
            __syncthreads();
            vf(s0 + 0.5f * hsub, s_yt);
            if (tid < HID) {
                float k2 = s_f[tid];
                s_ks[tid] += 2.f * k2;
                s_yt[tid] = fmaf(0.5f * hsub, k2, s_y[tid]);
            }
            __syncthreads();
            vf(s0 + 0.5f * hsub, s_yt);
            if (tid < HID) {
                float k3 = s_f[tid];
                s_ks[tid] += 2.f * k3;
                s_yt[tid] = fmaf(hsub, k3, s_y[tid]);
            }
            __syncthreads();
            vf(s0 + hsub, s_yt);
            if (tid < HID) {
                s_y[tid] = fmaf(hsub * (1.f / 6.f), s_ks[tid] + s_f[tid], s_y[tid]);
            }
            __syncthreads();
        }

        // readout t = iv + 1
        mvw<2, HID, ACT_NONE>(lW, s_y, lb, out + (b * T_LEN + iv + 1) * OBS);
    }
}

// ---------------- launch ------------------------------------------------------
static const int SMEM_FLOATS = 3 * WID * WID + T_LEN * CC + FOUT + WID + 3 * WID
                               + 2 * WID + 4 * HID + 4 * 36;
static const int SMEM_BYTES = SMEM_FLOATS * (int)sizeof(float);

extern "C" void kernel_launch(void* const* d_in, const int* in_sizes, int n_in,
                              void* d_out, int out_size) {
    const float* ts  = (const float*)d_in[0];
    const float* ys  = (const float*)d_in[1];
    const float* iW0 = (const float*)d_in[2];
    const float* ib0 = (const float*)d_in[3];
    const float* iWh = (const float*)d_in[4];
    const float* ibh = (const float*)d_in[5];
    const float* iWo = (const float*)d_in[6];
    const float* ibo = (const float*)d_in[7];
    const float* fW0 = (const float*)d_in[8];
    const float* fb0 = (const float*)d_in[9];
    const float* fWh = (const float*)d_in[10];
    const float* fbh = (const float*)d_in[11];
    const float* fWo = (const float*)d_in[12];
    const float* fbo = (const float*)d_in[13];
    const float* lW  = (const float*)d_in[14];
    const float* lb  = (const float*)d_in[15];
    float* out = (float*)d_out;

    cudaFuncSetAttribute(ncde_main, cudaFuncAttributeMaxDynamicSharedMemorySize, SMEM_BYTES);

    prep_fwo<<<132, 256>>>(fWo);
    ncde_main<<<64, NTH, SMEM_BYTES>>>(ts, ys, iW0, ib0, iWh, ibh, iWo, ibo,
                                       fW0, fb0, fWh, fbh, fbo, lW, lb, out);
}

// round 5
// speedup vs baseline: 1.8991x; 1.3172x over previous
#include <cuda_runtime.h>
#include <cuda_fp16.h>
#include <stdint.h>
#include <math.h>

// ---------------- problem constants ------------------------------------------
#define NTH   512
#define T_LEN 128
#define OBS   32
#define CC    33
#define HID   64
#define WID   128
#define FOUT  2112

#define ACT_NONE 0
#define ACT_RELU 1
#define ACT_SP   2

// fWo fp16, cluster-split warp-interleaved chunk layout.
// chunk = (((r*16 + w)*33 + c)*32 + lane), 8 halves per chunk.
// h = r*32 + w*2 + (lane>>4), p = lane&15, half j -> k = p*8 + j.
__device__ __align__(16) __half g_fWoH[FOUT * WID];

__global__ void prep_fwo(const float* __restrict__ fWo) {
    int chunk = blockIdx.x * blockDim.x + threadIdx.x;   // 33792 chunks
    if (chunk >= (FOUT * WID) / 8) return;
    int lane = chunk & 31;
    int t = chunk >> 5;            // (r*16+w)*33 + c
    int c = t % 33;
    int rw = t / 33;
    int w = rw & 15;
    int r = rw >> 4;
    int h = r * 32 + w * 2 + (lane >> 4);
    int p = lane & 15;
#pragma unroll
    for (int j = 0; j < 8; j++) {
        int k = p * 8 + j;
        g_fWoH[(size_t)chunk * 8 + j] = __float2half(fWo[(h * 33 + c) * WID + k]);
    }
}

// ---------------- small device helpers ---------------------------------------
__device__ __forceinline__ uint32_t s2u(const void* p) {
    return (uint32_t)__cvta_generic_to_shared(p);
}
__device__ __forceinline__ void bar_init(uint32_t addr, uint32_t count) {
    asm volatile("mbarrier.init.shared.b64 [%0], %1;" :: "r"(addr), "r"(count) : "memory");
}
__device__ __forceinline__ void bar_arrive_peer(uint32_t local_bar, uint32_t peer) {
    asm volatile(
        "{\n\t.reg .b32 ra;\n\t"
        "mapa.shared::cluster.u32 ra, %0, %1;\n\t"
        "mbarrier.arrive.release.cluster.shared::cluster.b64 _, [ra];\n\t}"
        :: "r"(local_bar), "r"(peer) : "memory");
}
__device__ __forceinline__ void st_peer_f32(uint32_t local_addr, uint32_t peer, float v) {
    asm volatile(
        "{\n\t.reg .b32 ra;\n\t"
        "mapa.shared::cluster.u32 ra, %0, %1;\n\t"
        "st.shared::cluster.f32 [ra], %2;\n\t}"
        :: "r"(local_addr), "r"(peer), "f"(v) : "memory");
}
__device__ __forceinline__ void bar_wait(uint32_t addr, uint32_t parity) {
    asm volatile(
        "{\n\t.reg .pred P;\n"
        "W%=:\n\t"
        "mbarrier.try_wait.parity.acquire.cluster.shared::cta.b64 P, [%0], %1, 0x989680;\n\t"
        "@!P bra W%=;\n\t}"
        :: "r"(addr), "r"(parity) : "memory");
}
__device__ __forceinline__ uint32_t ctarank() {
    uint32_t r;
    asm("mov.u32 %0, %%cluster_ctarank;" : "=r"(r));
    return r;
}

__device__ __forceinline__ float softplus_f(float x) {
    return fmaxf(x, 0.f) + __logf(1.f + __expf(-fabsf(x)));
}

// full-width warp-coop matvec (redundant work, init MLP / readout only)
template <int OPW, int I, int ACT>
__device__ __forceinline__ void mvw(const float* __restrict__ W,
                                    const float* __restrict__ x,
                                    const float* __restrict__ bias,
                                    float* __restrict__ outv) {
    constexpr int NJ = (I + 31) / 32;
    const int w = threadIdx.x >> 5;
    const int l = threadIdx.x & 31;
    float xr[NJ];
#pragma unroll
    for (int j = 0; j < NJ; j++) {
        int k = l + 32 * j;
        xr[j] = (k < I) ? x[k] : 0.f;
    }
    float acc[OPW];
#pragma unroll
    for (int oo = 0; oo < OPW; oo++) {
        const float* row = W + (w * OPW + oo) * I;
        float a = 0.f;
#pragma unroll
        for (int j = 0; j < NJ; j++) {
            int k = l + 32 * j;
            if (k < I) a = fmaf(row[k], xr[j], a);
        }
        acc[oo] = a;
    }
#pragma unroll
    for (int d = 16; d >= 1; d >>= 1)
#pragma unroll
        for (int oo = 0; oo < OPW; oo++)
            acc[oo] += __shfl_xor_sync(0xFFFFFFFFu, acc[oo], d);
    if (l < OPW) {
        float v = acc[l] + bias[w * OPW + l];
        if (ACT == ACT_RELU) v = fmaxf(v, 0.f);
        if (ACT == ACT_SP)   v = softplus_f(v);
        outv[w * OPW + l] = v;
    }
}

// half-width layer: this CTA computes 64 of 128 outputs, writes local + peer,
// arrives on peer's barH. Caller must __syncthreads() + bar_wait afterwards.
template <int I, int ACT>
__device__ __forceinline__ void layer_half(const float* __restrict__ W,   // 64 rows x I (local rows)
                                           const float* __restrict__ x,   // I full
                                           const float* __restrict__ bias,// 64 local
                                           float* __restrict__ outv,      // 128 full
                                           uint32_t outv_u32, uint32_t barH,
                                           int rank, uint32_t peer) {
    constexpr int NJ = (I + 31) / 32;
    const int w = threadIdx.x >> 5;
    const int l = threadIdx.x & 31;
    float xr[NJ];
#pragma unroll
    for (int j = 0; j < NJ; j++) {
        int k = l + 32 * j;
        xr[j] = (k < I) ? x[k] : 0.f;
    }
    float acc[4];
#pragma unroll
    for (int oo = 0; oo < 4; oo++) {
        const float* row = W + (w * 4 + oo) * I;
        float a = 0.f;
#pragma unroll
        for (int j = 0; j < NJ; j++) {
            int k = l + 32 * j;
            if (k < I) a = fmaf(row[k], xr[j], a);
        }
        acc[oo] = a;
    }
#pragma unroll
    for (int d = 16; d >= 1; d >>= 1)
#pragma unroll
        for (int oo = 0; oo < 4; oo++)
            acc[oo] += __shfl_xor_sync(0xFFFFFFFFu, acc[oo], d);
    if (l < 4) {
        float v = acc[l] + bias[w * 4 + l];
        if (ACT == ACT_RELU) v = fmaxf(v, 0.f);
        if (ACT == ACT_SP)   v = softplus_f(v);
        int og = rank * 64 + w * 4 + l;
        outv[og] = v;
        st_peer_f32(outv_u32 + og * 4, peer, v);
        bar_arrive_peer(barH, peer);   // maps to peer's barH (same smem offset)
    }
}

__global__ void __launch_bounds__(NTH, 1) __cluster_dims__(2, 1, 1)
ncde_main(const float* __restrict__ ts, const float* __restrict__ ys,
          const float* __restrict__ iW0, const float* __restrict__ ib0,
          const float* __restrict__ iWh, const float* __restrict__ ibh,
          const float* __restrict__ iWo, const float* __restrict__ ibo,
          const float* __restrict__ fW0, const float* __restrict__ fb0g,
          const float* __restrict__ fWh, const float* __restrict__ fbhg,
          const float* __restrict__ fbo, const float* __restrict__ lW,
          const float* __restrict__ lb, float* __restrict__ out) {
    extern __shared__ __align__(16) char smraw[];
    float* s_fWhH = (float*)(smraw + 16);            // 3*64*128 = 24576 floats
    float* s_fW0H = s_fWhH + 3 * 64 * WID;           // 64*64 = 4096
    float* s_tys  = s_fW0H + 64 * 64;                // 4224
    float* s_fboH = s_tys + T_LEN * CC;              // 32*33 = 1056
    float* s_fbh  = s_fboH + 32 * CC;                // 384 (full)
    float* s_fb0  = s_fbh + 3 * WID;                 // 128 (full)
    float* s_ha   = s_fb0 + WID;                     // 128
    float* s_hb   = s_ha + WID;                      // 128
    float* s_y    = s_hb + WID;                      // 64
    float* s_yt   = s_y + HID;                       // 64
    float* s_ks   = s_yt + HID;                      // 64
    float* s_f    = s_ks + HID;                      // 64
    float* s_xd   = s_f + HID;                       // 36
    float* s_d0   = s_xd + 36;                       // 36
    float* s_cc   = s_d0 + 36;                       // 36
    float* s_bb   = s_cc + 36;                       // 36

    const int tid = threadIdx.x;
    const int b = blockIdx.x >> 1;
    const int rank = (int)ctarank();
    const uint32_t peer = (uint32_t)(rank ^ 1);
    const int wrp = tid >> 5;
    const int lane = tid & 31;
    const int hl = tid >> 4;          // 0..31 local h row
    const int p = tid & 15;           // k-sixteenth

    const uint32_t barH = s2u(smraw);
    const uint32_t barF = s2u(smraw) + 8;
    const uint32_t u_ha = s2u(s_ha);
    const uint32_t u_hb = s2u(s_hb);
    const uint32_t u_f  = s2u(s_f);

    if (tid == 0) { bar_init(barH, 64); bar_init(barF, 32); }
    __syncthreads();
    asm volatile("barrier.cluster.arrive.aligned;" ::: "memory");
    asm volatile("barrier.cluster.wait.aligned;" ::: "memory");

    // --- stage per-rank weight halves + tys + biases --------------------------
    for (int i = tid; i < 3 * 64 * WID / 4; i += NTH) {
        int l = i / (64 * 32);
        int rem = i - l * 64 * 32;
        int row = rem >> 5, c4 = rem & 31;
        ((float4*)s_fWhH)[i] =
            ((const float4*)(fWh + (size_t)(l * WID + rank * 64 + row) * WID))[c4];
    }
    for (int i = tid; i < 64 * 64 / 4; i += NTH)
        ((float4*)s_fW0H)[i] = ((const float4*)(fW0 + rank * 64 * HID))[i];
    for (int i = tid; i < T_LEN * CC; i += NTH) {
        int t = i / CC, c = i - t * CC;
        s_tys[i] = (c == 0) ? ts[t] : ys[(b * T_LEN + t) * OBS + (c - 1)];
    }
    for (int i = tid; i < 32 * CC; i += NTH) s_fboH[i] = fbo[rank * 32 * CC + i];
    if (tid < 3 * WID) s_fbh[tid] = fbhg[tid];
    if (tid < WID)     s_fb0[tid] = fb0g[tid];
    __syncthreads();

    int phH = 0, phF = 0;

    // --- initial MLP (redundant in both CTAs) -> y0 ---------------------------
    mvw<8, CC, ACT_RELU>(iW0, s_tys, ib0, s_ha);                        __syncthreads();
    mvw<8, WID, ACT_RELU>(iWh,         s_ha, ibh,           s_hb);      __syncthreads();
    mvw<8, WID, ACT_RELU>(iWh + 16384, s_hb, ibh + WID,     s_ha);      __syncthreads();
    mvw<8, WID, ACT_RELU>(iWh + 32768, s_ha, ibh + 2 * WID, s_hb);      __syncthreads();
    mvw<4, WID, ACT_NONE>(iWo, s_hb, ibo, s_y);                         __syncthreads();

    if (rank == 0) mvw<2, HID, ACT_NONE>(lW, s_y, lb, out + (size_t)(b * T_LEN) * OBS);

    // --- vector field ----------------------------------------------------------
    auto vf = [&](float s, const float* __restrict__ yy) {
        if (tid < CC)
            s_xd[tid] = s_d0[tid] + 2.f * s_cc[tid] * s + 3.f * s_bb[tid] * s * s;
        layer_half<HID, ACT_SP>(s_fW0H, yy, s_fb0 + rank * 64, s_ha, u_ha, barH, rank, peer);
        __syncthreads(); bar_wait(barH, phH & 1); phH++;
        layer_half<WID, ACT_SP>(s_fWhH,             s_ha, s_fbh + rank * 64,           s_hb, u_hb, barH, rank, peer);
        __syncthreads(); bar_wait(barH, phH & 1); phH++;
        layer_half<WID, ACT_SP>(s_fWhH + 64 * WID,  s_hb, s_fbh + WID + rank * 64,     s_ha, u_ha, barH, rank, peer);
        __syncthreads(); bar_wait(barH, phH & 1); phH++;
        layer_half<WID, ACT_SP>(s_fWhH + 128 * WID, s_ha, s_fbh + 2 * WID + rank * 64, s_hb, u_hb, barH, rank, peer);
        __syncthreads(); bar_wait(barH, phH & 1); phH++;

        // ---- fp16 fWo (this CTA's 32 h rows), fused bias+tanh+contraction ----
        {
            const uint4* P = ((const uint4*)g_fWoH)
                             + ((size_t)(rank * 16 + wrp) * 33) * 32 + lane;
            float xk[8];
#pragma unroll
            for (int j = 0; j < 8; j++) xk[j] = s_hb[p * 8 + j];
            float z[33];
#pragma unroll
            for (int c = 0; c < 33; c++) {
                uint4 rr = P[c * 32];
                const __half2* hh = (const __half2*)&rr;
                float a = 0.f;
#pragma unroll
                for (int q = 0; q < 4; q++) {
                    float2 f2 = __half22float2(hh[q]);
                    a = fmaf(f2.x, xk[2 * q], a);
                    a = fmaf(f2.y, xk[2 * q + 1], a);
                }
                z[c] = a;
            }
#pragma unroll
            for (int d = 1; d <= 8; d <<= 1)
#pragma unroll
                for (int c = 0; c < 33; c++)
                    z[c] += __shfl_xor_sync(0xFFFFFFFFu, z[c], d);
            // lane p handles channels p, p+16 (p==0 also 32)
            float part;
            {
                float zc = z[p] + s_fboH[hl * CC + p];
                part = tanhf(zc) * s_xd[p];
                zc = z[p + 16] + s_fboH[hl * CC + p + 16];
                part = fmaf(tanhf(zc), s_xd[p + 16], part);
                if (p == 0) {
                    zc = z[32] + s_fboH[hl * CC + 32];
                    part = fmaf(tanhf(zc), s_xd[32], part);
                }
            }
#pragma unroll
            for (int d = 1; d <= 8; d <<= 1)
                part += __shfl_xor_sync(0xFFFFFFFFu, part, d);
            if (p == 0) {
                int hg = rank * 32 + hl;
                s_f[hg] = part;
                st_peer_f32(u_f + hg * 4, peer, part);
                bar_arrive_peer(barF, peer);
            }
            __syncthreads();
            bar_wait(barF, phF & 1); phF++;
        }
    };

    // --- interval scan + RK4 ---------------------------------------------------
    for (int iv = 0; iv < T_LEN - 1; iv++) {
        float dti = s_tys[(iv + 1) * CC] - s_tys[iv * CC];
        if (tid < CC) {
            float di = (s_tys[(iv + 1) * CC + tid] - s_tys[iv * CC + tid]) / dti;
            float d0v;
            if (iv == 0) {
                d0v = di;
            } else {
                float dtm = s_tys[iv * CC] - s_tys[(iv - 1) * CC];
                d0v = (s_tys[iv * CC + tid] - s_tys[(iv - 1) * CC + tid]) / dtm;
            }
            float d1v = di;
            s_d0[tid] = d0v;
            s_cc[tid] = (3.f * di - 2.f * d0v - d1v) / dti;
            s_bb[tid] = (d0v + d1v - 2.f * di) / (dti * dti);
        }
        __syncthreads();

        float hsub = dti * 0.25f;
#pragma unroll 1
        for (int sub = 0; sub < 4; sub++) {
            float s0 = hsub * (float)sub;
            vf(s0, s_y);
            if (tid < HID) {
                float k1 = s_f[tid];
                s_ks[tid] = k1;
                s_yt[tid] = fmaf(0.5f * hsub, k1, s_y[tid]);
            }
            __syncthreads();
            vf(s0 + 0.5f * hsub, s_yt);
            if (tid < HID) {
                float k2 = s_f[tid];
                s_ks[tid] += 2.f * k2;
                s_yt[tid] = fmaf(0.5f * hsub, k2, s_y[tid]);
            }
            __syncthreads();
            vf(s0 + 0.5f * hsub, s_yt);
            if (tid < HID) {
                float k3 = s_f[tid];
                s_ks[tid] += 2.f * k3;
                s_yt[tid] = fmaf(hsub, k3, s_y[tid]);
            }
            __syncthreads();
            vf(s0 + hsub, s_yt);
            if (tid < HID) {
                s_y[tid] = fmaf(hsub * (1.f / 6.f), s_ks[tid] + s_f[tid], s_y[tid]);
            }
            __syncthreads();
        }

        if (rank == 0) mvw<2, HID, ACT_NONE>(lW, s_y, lb, out + (size_t)(b * T_LEN + iv + 1) * OBS);
    }

    asm volatile("barrier.cluster.arrive.aligned;" ::: "memory");
    asm volatile("barrier.cluster.wait.aligned;" ::: "memory");
}

// ---------------- launch ------------------------------------------------------
static const int SMEM_FLOATS = 3 * 64 * WID + 64 * 64 + T_LEN * CC + 32 * CC
                               + 3 * WID + WID + 2 * WID + 4 * HID + 4 * 36;
static const int SMEM_BYTES = 16 + SMEM_FLOATS * (int)sizeof(float);

extern "C" void kernel_launch(void* const* d_in, const int* in_sizes, int n_in,
                              void* d_out, int out_size) {
    const float* ts  = (const float*)d_in[0];
    const float* ys  = (const float*)d_in[1];
    const float* iW0 = (const float*)d_in[2];
    const float* ib0 = (const float*)d_in[3];
    const float* iWh = (const float*)d_in[4];
    const float* ibh = (const float*)d_in[5];
    const float* iWo = (const float*)d_in[6];
    const float* ibo = (const float*)d_in[7];
    const float* fW0 = (const float*)d_in[8];
    const float* fb0 = (const float*)d_in[9];
    const float* fWh = (const float*)d_in[10];
    const float* fbh = (const float*)d_in[11];
    const float* fWo = (const float*)d_in[12];
    const float* fbo = (const float*)d_in[13];
    const float* lW  = (const float*)d_in[14];
    const float* lb  = (const float*)d_in[15];
    float* out = (float*)d_out;

    cudaFuncSetAttribute(ncde_main, cudaFuncAttributeMaxDynamicSharedMemorySize, SMEM_BYTES);

    prep_fwo<<<132, 256>>>(fWo);
    ncde_main<<<128, NTH, SMEM_BYTES>>>(ts, ys, iW0, ib0, iWh, ibh, iWo, ibo,
                                        fW0, fb0, fWh, fbh, fbo, lW, lb, out);
}

// round 6
// speedup vs baseline: 2.8514x; 1.5015x over previous
#include <cuda_runtime.h>
#include <cuda_fp16.h>
#include <stdint.h>
#include <math.h>

// ---------------- problem constants ------------------------------------------
#define NTH   512
#define T_LEN 128
#define OBS   32
#define CC    33
#define HID   64
#define WID   128
#define FOUT  2112

#define ACT_NONE 0
#define ACT_RELU 1
#define ACT_SP   2

// fWo fp16, re-tiled for the (h, channel-pair) decomposition.
// Region1 (32768 uint4): idx = (((r*16+w)*16 + kc)*2 + chI)*32 + l
//   h = r*32 + w*2 + (l>>4), p = l&15, c = chI ? p+16 : p, k = kc*8 + j
// Region2 (1024 uint4, channel 32): idx = 32768 + (r*16+w)*32 + l
//   h = r*32 + w*2 + (l>>4), c = 32, k = (l&15)*8 + j
__device__ __align__(16) __half g_fWoH[FOUT * WID];   // 33792 uint4 exactly

__global__ void prep_fwo(const float* __restrict__ fWo) {
    int idx = blockIdx.x * blockDim.x + threadIdx.x;
    if (idx >= 33792) return;
    __half hv[8];
    if (idx < 32768) {
        int l = idx & 31;
        int t = idx >> 5;
        int chI = t & 1;  t >>= 1;
        int kc = t & 15;  t >>= 4;
        int w = t & 15;
        int r = t >> 4;
        int h = r * 32 + w * 2 + (l >> 4);
        int p = l & 15;
        int c = chI ? (p + 16) : p;
#pragma unroll
        for (int j = 0; j < 8; j++)
            hv[j] = __float2half(fWo[(h * CC + c) * WID + kc * 8 + j]);
    } else {
        int i2 = idx - 32768;
        int l = i2 & 31;
        int rw = i2 >> 5;
        int w = rw & 15;
        int r = rw >> 4;
        int h = r * 32 + w * 2 + (l >> 4);
        int p = l & 15;
#pragma unroll
        for (int j = 0; j < 8; j++)
            hv[j] = __float2half(fWo[(h * CC + 32) * WID + p * 8 + j]);
    }
    ((uint4*)g_fWoH)[idx] = *(const uint4*)hv;
}

// ---------------- small device helpers ---------------------------------------
__device__ __forceinline__ uint32_t s2u(const void* p) {
    return (uint32_t)__cvta_generic_to_shared(p);
}
__device__ __forceinline__ void bar_init(uint32_t addr, uint32_t count) {
    asm volatile("mbarrier.init.shared.b64 [%0], %1;" :: "r"(addr), "r"(count) : "memory");
}
__device__ __forceinline__ void bar_arrive_peer(uint32_t local_bar, uint32_t peer) {
    asm volatile(
        "{\n\t.reg .b32 ra;\n\t"
        "mapa.shared::cluster.u32 ra, %0, %1;\n\t"
        "mbarrier.arrive.release.cluster.shared::cluster.b64 _, [ra];\n\t}"
        :: "r"(local_bar), "r"(peer) : "memory");
}
__device__ __forceinline__ void st_peer_f32(uint32_t local_addr, uint32_t peer, float v) {
    asm volatile(
        "{\n\t.reg .b32 ra;\n\t"
        "mapa.shared::cluster.u32 ra, %0, %1;\n\t"
        "st.shared::cluster.f32 [ra], %2;\n\t}"
        :: "r"(local_addr), "r"(peer), "f"(v) : "memory");
}
__device__ __forceinline__ void bar_wait(uint32_t addr, uint32_t parity) {
    asm volatile(
        "{\n\t.reg .pred P;\n"
        "W%=:\n\t"
        "mbarrier.try_wait.parity.acquire.cluster.shared::cta.b64 P, [%0], %1, 0x989680;\n\t"
        "@!P bra W%=;\n\t}"
        :: "r"(addr), "r"(parity) : "memory");
}
__device__ __forceinline__ uint32_t ctarank() {
    uint32_t r;
    asm("mov.u32 %0, %%cluster_ctarank;" : "=r"(r));
    return r;
}

__device__ __forceinline__ float softplus_f(float x) {
    return fmaxf(x, 0.f) + __logf(1.f + __expf(-fabsf(x)));
}
__device__ __forceinline__ float tanh_f(float x) {
    float e = __expf(-2.0f * fabsf(x));
    float t = __fdividef(1.0f - e, 1.0f + e);
    return copysignf(t, x);
}
// dot of 8 fp16 weights against 8 fp32 activations (two float4)
__device__ __forceinline__ float dot8(uint4 wv, float4 xa, float4 xb, float acc) {
    const __half2* hh = (const __half2*)&wv;
    float2 f0 = __half22float2(hh[0]);
    float2 f1 = __half22float2(hh[1]);
    float2 f2 = __half22float2(hh[2]);
    float2 f3 = __half22float2(hh[3]);
    acc = fmaf(f0.x, xa.x, acc); acc = fmaf(f0.y, xa.y, acc);
    acc = fmaf(f1.x, xa.z, acc); acc = fmaf(f1.y, xa.w, acc);
    acc = fmaf(f2.x, xb.x, acc); acc = fmaf(f2.y, xb.y, acc);
    acc = fmaf(f3.x, xb.z, acc); acc = fmaf(f3.y, xb.w, acc);
    return acc;
}

// full-width warp-coop matvec: 16 warps, warp w -> outputs [w*OPW, (w+1)*OPW)
template <int OPW, int I, int ACT>
__device__ __forceinline__ void mvw(const float* __restrict__ W,
                                    const float* __restrict__ x,
                                    const float* __restrict__ bias,
                                    float* __restrict__ outv) {
    constexpr int NJ = (I + 31) / 32;
    const int w = threadIdx.x >> 5;
    const int l = threadIdx.x & 31;
    float xr[NJ];
#pragma unroll
    for (int j = 0; j < NJ; j++) {
        int k = l + 32 * j;
        xr[j] = (k < I) ? x[k] : 0.f;
    }
    float acc[OPW];
#pragma unroll
    for (int oo = 0; oo < OPW; oo++) {
        const float* row = W + (w * OPW + oo) * I;
        float a = 0.f;
#pragma unroll
        for (int j = 0; j < NJ; j++) {
            int k = l + 32 * j;
            if (k < I) a = fmaf(row[k], xr[j], a);
        }
        acc[oo] = a;
    }
#pragma unroll
    for (int d = 16; d >= 1; d >>= 1)
#pragma unroll
        for (int oo = 0; oo < OPW; oo++)
            acc[oo] += __shfl_xor_sync(0xFFFFFFFFu, acc[oo], d);
    if (l < OPW) {
        float v = acc[l] + bias[w * OPW + l];
        if (ACT == ACT_RELU) v = fmaxf(v, 0.f);
        if (ACT == ACT_SP)   v = softplus_f(v);
        outv[w * OPW + l] = v;
    }
}

__global__ void __launch_bounds__(NTH, 1) __cluster_dims__(2, 1, 1)
ncde_main(const float* __restrict__ ts, const float* __restrict__ ys,
          const float* __restrict__ iW0, const float* __restrict__ ib0,
          const float* __restrict__ iWh, const float* __restrict__ ibh,
          const float* __restrict__ iWo, const float* __restrict__ ibo,
          const float* __restrict__ fW0, const float* __restrict__ fb0g,
          const float* __restrict__ fWh, const float* __restrict__ fbhg,
          const float* __restrict__ fbo, const float* __restrict__ lW,
          const float* __restrict__ lb, float* __restrict__ out) {
    extern __shared__ __align__(16) char smraw[];
    float* s_fWh  = (float*)(smraw + 16);            // 3*128*128 = 49152 floats
    float* s_tys  = s_fWh + 3 * WID * WID;           // 4224
    float* s_fboH = s_tys + T_LEN * CC;              // 32*33 = 1056 (this CTA's h rows)
    float* s_fbh  = s_fboH + 32 * CC;                // 384 (full)
    float* s_fb0  = s_fbh + 3 * WID;                 // 128 (full)
    float* s_ha   = s_fb0 + WID;                     // 128
    float* s_hb   = s_ha + WID;                      // 128
    float* s_y    = s_hb + WID;                      // 64
    float* s_yt   = s_y + HID;                       // 64
    float* s_ks   = s_yt + HID;                      // 64
    float* s_f    = s_ks + HID;                      // 64
    float* s_xd   = s_f + HID;                       // 36
    float* s_d0   = s_xd + 36;                       // 36
    float* s_cc   = s_d0 + 36;                       // 36
    float* s_bb   = s_cc + 36;                       // 36

    const int tid = threadIdx.x;
    const int b = blockIdx.x >> 1;
    const int rank = (int)ctarank();
    const uint32_t peer = (uint32_t)(rank ^ 1);
    const int wrp = tid >> 5;
    const int lane = tid & 31;
    const int hl = tid >> 4;          // 0..31 local h row
    const int p = tid & 15;           // channel id within pair-set

    const uint32_t barF = s2u(smraw);
    const uint32_t u_f  = s2u(s_f);

    if (tid == 0) bar_init(barF, 32);
    __syncthreads();
    asm volatile("barrier.cluster.arrive.aligned;" ::: "memory");
    asm volatile("barrier.cluster.wait.aligned;" ::: "memory");

    // --- stage full fWh + tys + biases ----------------------------------------
    {
        const float4* src = (const float4*)fWh;
        float4* dst = (float4*)s_fWh;
        for (int i = tid; i < 3 * WID * WID / 4; i += NTH) dst[i] = src[i];
    }
    for (int i = tid; i < T_LEN * CC; i += NTH) {
        int t = i / CC, c = i - t * CC;
        s_tys[i] = (c == 0) ? ts[t] : ys[(b * T_LEN + t) * OBS + (c - 1)];
    }
    for (int i = tid; i < 32 * CC; i += NTH) s_fboH[i] = fbo[rank * 32 * CC + i];
    if (tid < 3 * WID) s_fbh[tid] = fbhg[tid];
    if (tid < WID)     s_fb0[tid] = fb0g[tid];
    __syncthreads();

    int phF = 0;

    // --- initial MLP (redundant in both CTAs) -> y0 ---------------------------
    mvw<8, CC, ACT_RELU>(iW0, s_tys, ib0, s_ha);                        __syncthreads();
    mvw<8, WID, ACT_RELU>(iWh,         s_ha, ibh,           s_hb);      __syncthreads();
    mvw<8, WID, ACT_RELU>(iWh + 16384, s_hb, ibh + WID,     s_ha);      __syncthreads();
    mvw<8, WID, ACT_RELU>(iWh + 32768, s_ha, ibh + 2 * WID, s_hb);      __syncthreads();
    mvw<4, WID, ACT_NONE>(iWo, s_hb, ibo, s_y);                         __syncthreads();

    if (rank == 0) mvw<2, HID, ACT_NONE>(lW, s_y, lb, out + (size_t)(b * T_LEN) * OBS);

    // fWo pointers for this thread
    const uint4* W1  = ((const uint4*)g_fWoH) + (size_t)(rank * 16 + wrp) * 1024 + lane;
    const uint4* W2p = ((const uint4*)g_fWoH) + 32768 + (size_t)(rank * 16 + wrp) * 32 + lane;
    const int hg = rank * 32 + hl;    // global h row this thread contributes to

    // --- vector field ----------------------------------------------------------
    auto vf = [&](float s, const float* __restrict__ yy) {
        if (tid < CC)
            s_xd[tid] = s_d0[tid] + 2.f * s_cc[tid] * s + 3.f * s_bb[tid] * s * s;
        // hidden chain: full-width, redundant in both CTAs (no exchange)
        mvw<8, HID, ACT_SP>(fW0, yy, s_fb0, s_ha);                       __syncthreads();
        mvw<8, WID, ACT_SP>(s_fWh,         s_ha, s_fbh,           s_hb); __syncthreads();
        mvw<8, WID, ACT_SP>(s_fWh + 16384, s_hb, s_fbh + WID,     s_ha); __syncthreads();
        mvw<8, WID, ACT_SP>(s_fWh + 32768, s_ha, s_fbh + 2 * WID, s_hb); __syncthreads();

        // ---- fWo (this CTA's 32 h rows): shuffle-free channel-pair scheme ----
        {
            const float4* hb4 = (const float4*)s_hb;
            float z0a = 0.f, z0b = 0.f, z1a = 0.f, z1b = 0.f;
#pragma unroll
            for (int kc = 0; kc < 16; kc += 2) {
                float4 xa0 = hb4[kc * 2],     xb0 = hb4[kc * 2 + 1];
                float4 xa1 = hb4[kc * 2 + 2], xb1 = hb4[kc * 2 + 3];
                z0a = dot8(W1[kc * 64],      xa0, xb0, z0a);
                z1a = dot8(W1[kc * 64 + 32], xa0, xb0, z1a);
                z0b = dot8(W1[kc * 64 + 64], xa1, xb1, z0b);
                z1b = dot8(W1[kc * 64 + 96], xa1, xb1, z1b);
            }
            float z0 = z0a + z0b;
            float z1 = z1a + z1b;
            // channel 32: k-split partial, reduce over 16 lanes
            float z2 = dot8(*W2p, hb4[p * 2], hb4[p * 2 + 1], 0.f);
#pragma unroll
            for (int d = 1; d <= 8; d <<= 1)
                z2 += __shfl_xor_sync(0xFFFFFFFFu, z2, d);

            float part = tanh_f(z0 + s_fboH[hl * CC + p]) * s_xd[p];
            part = fmaf(tanh_f(z1 + s_fboH[hl * CC + p + 16]), s_xd[p + 16], part);
            if (p == 0)
                part = fmaf(tanh_f(z2 + s_fboH[hl * CC + 32]), s_xd[32], part);
#pragma unroll
            for (int d = 1; d <= 8; d <<= 1)
                part += __shfl_xor_sync(0xFFFFFFFFu, part, d);
            if (p == 0) {
                s_f[hg] = part;
                st_peer_f32(u_f + hg * 4, peer, part);
                bar_arrive_peer(barF, peer);
            }
            __syncthreads();
            bar_wait(barF, phF & 1); phF++;
        }
    };

    // --- interval scan + RK4 ---------------------------------------------------
    for (int iv = 0; iv < T_LEN - 1; iv++) {
        float dti = s_tys[(iv + 1) * CC] - s_tys[iv * CC];
        if (tid < CC) {
            float di = (s_tys[(iv + 1) * CC + tid] - s_tys[iv * CC + tid]) / dti;
            float d0v;
            if (iv == 0) {
                d0v = di;
            } else {
                float dtm = s_tys[iv * CC] - s_tys[(iv - 1) * CC];
                d0v = (s_tys[iv * CC + tid] - s_tys[(iv - 1) * CC + tid]) / dtm;
            }
            float d1v = di;
            s_d0[tid] = d0v;
            s_cc[tid] = (3.f * di - 2.f * d0v - d1v) / dti;
            s_bb[tid] = (d0v + d1v - 2.f * di) / (dti * dti);
        }
        __syncthreads();

        float hsub = dti * 0.25f;
#pragma unroll 1
        for (int sub = 0; sub < 4; sub++) {
            float s0 = hsub * (float)sub;
            vf(s0, s_y);
            if (tid < HID) {
                float k1 = s_f[tid];
                s_ks[tid] = k1;
                s_yt[tid] = fmaf(0.5f * hsub, k1, s_y[tid]);
            }
            __syncthreads();
            vf(s0 + 0.5f * hsub, s_yt);
            if (tid < HID) {
                float k2 = s_f[tid];
                s_ks[tid] += 2.f * k2;
                s_yt[tid] = fmaf(0.5f * hsub, k2, s_y[tid]);
            }
            __syncthreads();
            vf(s0 + 0.5f * hsub, s_yt);
            if (tid < HID) {
                float k3 = s_f[tid];
                s_ks[tid] += 2.f * k3;
                s_yt[tid] = fmaf(hsub, k3, s_y[tid]);
            }
            __syncthreads();
            vf(s0 + hsub, s_yt);
            if (tid < HID) {
                s_y[tid] = fmaf(hsub * (1.f / 6.f), s_ks[tid] + s_f[tid], s_y[tid]);
            }
            __syncthreads();
        }

        if (rank == 0) mvw<2, HID, ACT_NONE>(lW, s_y, lb, out + (size_t)(b * T_LEN + iv + 1) * OBS);
    }

    asm volatile("barrier.cluster.arrive.aligned;" ::: "memory");
    asm volatile("barrier.cluster.wait.aligned;" ::: "memory");
}

// ---------------- launch ------------------------------------------------------
static const int SMEM_FLOATS = 3 * WID * WID + T_LEN * CC + 32 * CC
                               + 3 * WID + WID + 2 * WID + 4 * HID + 4 * 36;
static const int SMEM_BYTES = 16 + SMEM_FLOATS * (int)sizeof(float);

extern "C" void kernel_launch(void* const* d_in, const int* in_sizes, int n_in,
                              void* d_out, int out_size) {
    const float* ts  = (const float*)d_in[0];
    const float* ys  = (const float*)d_in[1];
    const float* iW0 = (const float*)d_in[2];
    const float* ib0 = (const float*)d_in[3];
    const float* iWh = (const float*)d_in[4];
    const float* ibh = (const float*)d_in[5];
    const float* iWo = (const float*)d_in[6];
    const float* ibo = (const float*)d_in[7];
    const float* fW0 = (const float*)d_in[8];
    const float* fb0 = (const float*)d_in[9];
    const float* fWh = (const float*)d_in[10];
    const float* fbh = (const float*)d_in[11];
    const float* fWo = (const float*)d_in[12];
    const float* fbo = (const float*)d_in[13];
    const float* lW  = (const float*)d_in[14];
    const float* lb  = (const float*)d_in[15];
    float* out = (float*)d_out;

    cudaFuncSetAttribute(ncde_main, cudaFuncAttributeMaxDynamicSharedMemorySize, SMEM_BYTES);

    prep_fwo<<<132, 256>>>(fWo);
    ncde_main<<<128, NTH, SMEM_BYTES>>>(ts, ys, iW0, ib0, iWh, ibh, iWo, ibo,
                                        fW0, fb0, fWh, fbh, fbo, lW, lb, out);
}

// round 7
// speedup vs baseline: 3.8222x; 1.3405x over previous
#include <cuda_runtime.h>
#include <cuda_fp16.h>
#include <stdint.h>
#include <math.h>

// ---------------- problem constants ------------------------------------------
#define NTH   512
#define T_LEN 128
#define OBS   32
#define CC    33
#define HID   64
#define WID   128
#define FOUT  2112

#define ACT_NONE 0
#define ACT_RELU 1
#define ACT_SP   2

// fWo fp16, re-tiled for the (h, channel-pair) decomposition (unchanged from R6).
__device__ __align__(16) __half g_fWoH[FOUT * WID];   // 33792 uint4

// hidden-chain weights as half2, k-pair packed, column-major over outputs:
// g_fWhH2[(l*64 + kp)*128 + o] = (W[l][o][2kp], W[l][o][2kp+1])
__device__ __align__(16) __half2 g_fWhH2[3 * 64 * WID];
// g_fW0H2[kp*128 + o] = (fW0[o][2kp], fW0[o][2kp+1]), kp < 32
__device__ __align__(16) __half2 g_fW0H2[32 * WID];

__global__ void prep_fwo(const float* __restrict__ fWo) {
    int idx = blockIdx.x * blockDim.x + threadIdx.x;
    if (idx >= 33792) return;
    __half hv[8];
    if (idx < 32768) {
        int l = idx & 31;
        int t = idx >> 5;
        int chI = t & 1;  t >>= 1;
        int kc = t & 15;  t >>= 4;
        int w = t & 15;
        int r = t >> 4;
        int h = r * 32 + w * 2 + (l >> 4);
        int p = l & 15;
        int c = chI ? (p + 16) : p;
#pragma unroll
        for (int j = 0; j < 8; j++)
            hv[j] = __float2half(fWo[(h * CC + c) * WID + kc * 8 + j]);
    } else {
        int i2 = idx - 32768;
        int l = i2 & 31;
        int rw = i2 >> 5;
        int w = rw & 15;
        int r = rw >> 4;
        int h = r * 32 + w * 2 + (l >> 4);
        int p = l & 15;
#pragma unroll
        for (int j = 0; j < 8; j++)
            hv[j] = __float2half(fWo[(h * CC + 32) * WID + p * 8 + j]);
    }
    ((uint4*)g_fWoH)[idx] = *(const uint4*)hv;
}

__global__ void prep_h2(const float* __restrict__ fWh, const float* __restrict__ fW0) {
    int idx = blockIdx.x * blockDim.x + threadIdx.x;
    if (idx < 3 * 64 * WID) {
        int o = idx & 127;
        int t = idx >> 7;
        int kp = t & 63;
        int l = t >> 6;
        const float* row = fWh + ((size_t)(l * WID + o)) * WID;
        g_fWhH2[idx] = __floats2half2_rn(row[2 * kp], row[2 * kp + 1]);
    } else if (idx < 3 * 64 * WID + 32 * WID) {
        int i2 = idx - 3 * 64 * WID;
        int o = i2 & 127;
        int kp = i2 >> 7;
        const float* row = fW0 + (size_t)o * HID;
        g_fW0H2[i2] = __floats2half2_rn(row[2 * kp], row[2 * kp + 1]);
    }
}

// ---------------- small device helpers ---------------------------------------
__device__ __forceinline__ uint32_t s2u(const void* p) {
    return (uint32_t)__cvta_generic_to_shared(p);
}
__device__ __forceinline__ void bar_init(uint32_t addr, uint32_t count) {
    asm volatile("mbarrier.init.shared.b64 [%0], %1;" :: "r"(addr), "r"(count) : "memory");
}
__device__ __forceinline__ void bar_arrive_peer(uint32_t local_bar, uint32_t peer) {
    asm volatile(
        "{\n\t.reg .b32 ra;\n\t"
        "mapa.shared::cluster.u32 ra, %0, %1;\n\t"
        "mbarrier.arrive.release.cluster.shared::cluster.b64 _, [ra];\n\t}"
        :: "r"(local_bar), "r"(peer) : "memory");
}
__device__ __forceinline__ void st_peer_f32(uint32_t local_addr, uint32_t peer, float v) {
    asm volatile(
        "{\n\t.reg .b32 ra;\n\t"
        "mapa.shared::cluster.u32 ra, %0, %1;\n\t"
        "st.shared::cluster.f32 [ra], %2;\n\t}"
        :: "r"(local_addr), "r"(peer), "f"(v) : "memory");
}
__device__ __forceinline__ void bar_wait(uint32_t addr, uint32_t parity) {
    asm volatile(
        "{\n\t.reg .pred P;\n"
        "W%=:\n\t"
        "mbarrier.try_wait.parity.acquire.cluster.shared::cta.b64 P, [%0], %1, 0x989680;\n\t"
        "@!P bra W%=;\n\t}"
        :: "r"(addr), "r"(parity) : "memory");
}
__device__ __forceinline__ uint32_t ctarank() {
    uint32_t r;
    asm("mov.u32 %0, %%cluster_ctarank;" : "=r"(r));
    return r;
}

__device__ __forceinline__ float softplus_f(float x) {
    return fmaxf(x, 0.f) + __logf(1.f + __expf(-fabsf(x)));
}
__device__ __forceinline__ float tanh_f(float x) {
    float e = __expf(-2.0f * fabsf(x));
    float t = __fdividef(1.0f - e, 1.0f + e);
    return copysignf(t, x);
}
__device__ __forceinline__ float dot8(uint4 wv, float4 xa, float4 xb, float acc) {
    const __half2* hh = (const __half2*)&wv;
    float2 f0 = __half22float2(hh[0]);
    float2 f1 = __half22float2(hh[1]);
    float2 f2 = __half22float2(hh[2]);
    float2 f3 = __half22float2(hh[3]);
    acc = fmaf(f0.x, xa.x, acc); acc = fmaf(f0.y, xa.y, acc);
    acc = fmaf(f1.x, xa.z, acc); acc = fmaf(f1.y, xa.w, acc);
    acc = fmaf(f2.x, xb.x, acc); acc = fmaf(f2.y, xb.y, acc);
    acc = fmaf(f3.x, xb.z, acc); acc = fmaf(f3.y, xb.w, acc);
    return acc;
}

// shuffle-free fp16 hidden layer: 128 outputs, NKP k-pairs, 4-way k-split,
// smem partial reduce. Costs 2 __syncthreads.
template <int NKP, int ACT>
__device__ __forceinline__ void layer_h2(const __half2* __restrict__ Wc,  // [NKP][128]
                                         const float* __restrict__ x,    // 2*NKP floats
                                         const float* __restrict__ bias, // 128
                                         float* __restrict__ outv,       // 128
                                         float* __restrict__ s_part) {
    const int tid = threadIdx.x;
    const int o = tid & 127;
    const int p = tid >> 7;          // 0..3
    constexpr int JP = NKP / 4;
    const __half2* col = Wc + JP * p * 128 + o;
    const float2* x2 = (const float2*)x;
    float acc = 0.f;
#pragma unroll
    for (int j = 0; j < JP; j++) {
        float2 wf = __half22float2(col[j * 128]);
        float2 xv = x2[JP * p + j];
        acc = fmaf(wf.x, xv.x, acc);
        acc = fmaf(wf.y, xv.y, acc);
    }
    s_part[tid] = acc;
    __syncthreads();
    if (tid < 128) {
        float v = s_part[tid] + s_part[tid + 128] + s_part[tid + 256]
                + s_part[tid + 384] + bias[tid];
        if (ACT == ACT_RELU) v = fmaxf(v, 0.f);
        if (ACT == ACT_SP)   v = softplus_f(v);
        outv[tid] = v;
    }
    __syncthreads();
}

// full-width fp32 warp-coop matvec (cold paths: init MLP, readout)
template <int OPW, int I, int ACT>
__device__ __forceinline__ void mvw(const float* __restrict__ W,
                                    const float* __restrict__ x,
                                    const float* __restrict__ bias,
                                    float* __restrict__ outv) {
    constexpr int NJ = (I + 31) / 32;
    const int w = threadIdx.x >> 5;
    const int l = threadIdx.x & 31;
    float xr[NJ];
#pragma unroll
    for (int j = 0; j < NJ; j++) {
        int k = l + 32 * j;
        xr[j] = (k < I) ? x[k] : 0.f;
    }
    float acc[OPW];
#pragma unroll
    for (int oo = 0; oo < OPW; oo++) {
        const float* row = W + (w * OPW + oo) * I;
        float a = 0.f;
#pragma unroll
        for (int j = 0; j < NJ; j++) {
            int k = l + 32 * j;
            if (k < I) a = fmaf(row[k], xr[j], a);
        }
        acc[oo] = a;
    }
#pragma unroll
    for (int d = 16; d >= 1; d >>= 1)
#pragma unroll
        for (int oo = 0; oo < OPW; oo++)
            acc[oo] += __shfl_xor_sync(0xFFFFFFFFu, acc[oo], d);
    if (l < OPW) {
        float v = acc[l] + bias[w * OPW + l];
        if (ACT == ACT_RELU) v = fmaxf(v, 0.f);
        if (ACT == ACT_SP)   v = softplus_f(v);
        outv[w * OPW + l] = v;
    }
}

__global__ void __launch_bounds__(NTH, 1) __cluster_dims__(2, 1, 1)
ncde_main(const float* __restrict__ ts, const float* __restrict__ ys,
          const float* __restrict__ iW0, const float* __restrict__ ib0,
          const float* __restrict__ iWh, const float* __restrict__ ibh,
          const float* __restrict__ iWo, const float* __restrict__ ibo,
          const float* __restrict__ fb0g, const float* __restrict__ fbhg,
          const float* __restrict__ fbo, const float* __restrict__ lW,
          const float* __restrict__ lb, float* __restrict__ out) {
    extern __shared__ __align__(16) char smraw[];
    __half2* s_Wh = (__half2*)(smraw + 16);          // 3*64*128 half2 = 98304 B
    __half2* s_W0 = s_Wh + 3 * 64 * WID;             // 32*128 half2 = 16384 B
    float* s_tys  = (float*)(s_W0 + 32 * WID);       // 4224 floats
    float* s_fboH = s_tys + T_LEN * CC;              // 1056
    float* s_part = s_fboH + 32 * CC;                // 512
    float* s_fbh  = s_part + NTH;                    // 384
    float* s_fb0  = s_fbh + 3 * WID;                 // 128
    float* s_ha   = s_fb0 + WID;                     // 128
    float* s_hb   = s_ha + WID;                      // 128
    float* s_y    = s_hb + WID;                      // 64
    float* s_yt   = s_y + HID;                       // 64
    float* s_ks   = s_yt + HID;                      // 64
    float* s_f    = s_ks + HID;                      // 64
    float* s_xd   = s_f + HID;                       // 36
    float* s_d0   = s_xd + 36;                       // 36
    float* s_cc   = s_d0 + 36;                       // 36
    float* s_bb   = s_cc + 36;                       // 36

    const int tid = threadIdx.x;
    const int b = blockIdx.x >> 1;
    const int rank = (int)ctarank();
    const uint32_t peer = (uint32_t)(rank ^ 1);
    const int wrp = tid >> 5;
    const int lane = tid & 31;
    const int hl = tid >> 4;          // 0..31 local h row
    const int p = tid & 15;           // channel id within pair-set

    const uint32_t barF = s2u(smraw);
    const uint32_t u_f  = s2u(s_f);

    if (tid == 0) bar_init(barF, 32);
    __syncthreads();
    asm volatile("barrier.cluster.arrive.aligned;" ::: "memory");
    asm volatile("barrier.cluster.wait.aligned;" ::: "memory");

    // --- stage fp16 hidden weights + tys + biases ------------------------------
    {
        const uint4* src = (const uint4*)g_fWhH2;
        uint4* dst = (uint4*)s_Wh;
        for (int i = tid; i < 3 * 64 * WID / 4; i += NTH) dst[i] = src[i];
        const uint4* s2 = (const uint4*)g_fW0H2;
        uint4* d2 = (uint4*)s_W0;
        for (int i = tid; i < 32 * WID / 4; i += NTH) d2[i] = s2[i];
    }
    for (int i = tid; i < T_LEN * CC; i += NTH) {
        int t = i / CC, c = i - t * CC;
        s_tys[i] = (c == 0) ? ts[t] : ys[(b * T_LEN + t) * OBS + (c - 1)];
    }
    for (int i = tid; i < 32 * CC; i += NTH) s_fboH[i] = fbo[rank * 32 * CC + i];
    if (tid < 3 * WID) s_fbh[tid] = fbhg[tid];
    if (tid < WID)     s_fb0[tid] = fb0g[tid];
    __syncthreads();

    int phF = 0;

    // --- initial MLP (redundant in both CTAs, fp32, cold) -> y0 ----------------
    mvw<8, CC, ACT_RELU>(iW0, s_tys, ib0, s_ha);                        __syncthreads();
    mvw<8, WID, ACT_RELU>(iWh,         s_ha, ibh,           s_hb);      __syncthreads();
    mvw<8, WID, ACT_RELU>(iWh + 16384, s_hb, ibh + WID,     s_ha);      __syncthreads();
    mvw<8, WID, ACT_RELU>(iWh + 32768, s_ha, ibh + 2 * WID, s_hb);      __syncthreads();
    mvw<4, WID, ACT_NONE>(iWo, s_hb, ibo, s_y);                         __syncthreads();

    if (rank == 0) mvw<2, HID, ACT_NONE>(lW, s_y, lb, out + (size_t)(b * T_LEN) * OBS);

    // fWo pointers for this thread
    const uint4* W1  = ((const uint4*)g_fWoH) + (size_t)(rank * 16 + wrp) * 1024 + lane;
    const uint4* W2p = ((const uint4*)g_fWoH) + 32768 + (size_t)(rank * 16 + wrp) * 32 + lane;
    const int hg = rank * 32 + hl;

    // --- vector field -----------------------------------------------------------
    auto vf = [&](float s, const float* __restrict__ yy) {
        if (tid < CC)
            s_xd[tid] = s_d0[tid] + 2.f * s_cc[tid] * s + 3.f * s_bb[tid] * s * s;
        // hidden chain: fp16 smem weights, shuffle-free
        layer_h2<32, ACT_SP>(s_W0, yy, s_fb0, s_ha, s_part);
        layer_h2<64, ACT_SP>(s_Wh,            s_ha, s_fbh,           s_hb, s_part);
        layer_h2<64, ACT_SP>(s_Wh + 64 * WID, s_hb, s_fbh + WID,     s_ha, s_part);
        layer_h2<64, ACT_SP>(s_Wh + 128 * WID, s_ha, s_fbh + 2 * WID, s_hb, s_part);

        // ---- fWo (this CTA's 32 h rows): channel-pair scheme ----
        {
            const float4* hb4 = (const float4*)s_hb;
            float z0a = 0.f, z0b = 0.f, z1a = 0.f, z1b = 0.f;
#pragma unroll
            for (int kc = 0; kc < 16; kc += 2) {
                float4 xa0 = hb4[kc * 2],     xb0 = hb4[kc * 2 + 1];
                float4 xa1 = hb4[kc * 2 + 2], xb1 = hb4[kc * 2 + 3];
                z0a = dot8(W1[kc * 64],      xa0, xb0, z0a);
                z1a = dot8(W1[kc * 64 + 32], xa0, xb0, z1a);
                z0b = dot8(W1[kc * 64 + 64], xa1, xb1, z0b);
                z1b = dot8(W1[kc * 64 + 96], xa1, xb1, z1b);
            }
            float z0 = z0a + z0b;
            float z1 = z1a + z1b;
            float z2 = dot8(*W2p, hb4[p * 2], hb4[p * 2 + 1], 0.f);
#pragma unroll
            for (int d = 1; d <= 8; d <<= 1)
                z2 += __shfl_xor_sync(0xFFFFFFFFu, z2, d);

            float part = tanh_f(z0 + s_fboH[hl * CC + p]) * s_xd[p];
            part = fmaf(tanh_f(z1 + s_fboH[hl * CC + p + 16]), s_xd[p + 16], part);
            if (p == 0)
                part = fmaf(tanh_f(z2 + s_fboH[hl * CC + 32]), s_xd[32], part);
#pragma unroll
            for (int d = 1; d <= 8; d <<= 1)
                part += __shfl_xor_sync(0xFFFFFFFFu, part, d);
            if (p == 0) {
                s_f[hg] = part;
                st_peer_f32(u_f + hg * 4, peer, part);
                bar_arrive_peer(barF, peer);
            }
            __syncthreads();
            bar_wait(barF, phF & 1); phF++;
        }
    };

    // --- interval scan + RK4 -----------------------------------------------------
    for (int iv = 0; iv < T_LEN - 1; iv++) {
        float dti = s_tys[(iv + 1) * CC] - s_tys[iv * CC];
        if (tid < CC) {
            float di = (s_tys[(iv + 1) * CC + tid] - s_tys[iv * CC + tid]) / dti;
            float d0v;
            if (iv == 0) {
                d0v = di;
            } else {
                float dtm = s_tys[iv * CC] - s_tys[(iv - 1) * CC];
                d0v = (s_tys[iv * CC + tid] - s_tys[(iv - 1) * CC + tid]) / dtm;
            }
            float d1v = di;
            s_d0[tid] = d0v;
            s_cc[tid] = (3.f * di - 2.f * d0v - d1v) / dti;
            s_bb[tid] = (d0v + d1v - 2.f * di) / (dti * dti);
        }
        __syncthreads();

        float hsub = dti * 0.25f;
#pragma unroll 1
        for (int sub = 0; sub < 4; sub++) {
            float s0 = hsub * (float)sub;
            vf(s0, s_y);
            if (tid < HID) {
                float k1 = s_f[tid];
                s_ks[tid] = k1;
                s_yt[tid] = fmaf(0.5f * hsub, k1, s_y[tid]);
            }
            __syncthreads();
            vf(s0 + 0.5f * hsub, s_yt);
            if (tid < HID) {
                float k2 = s_f[tid];
                s_ks[tid] += 2.f * k2;
                s_yt[tid] = fmaf(0.5f * hsub, k2, s_y[tid]);
            }
            __syncthreads();
            vf(s0 + 0.5f * hsub, s_yt);
            if (tid < HID) {
                float k3 = s_f[tid];
                s_ks[tid] += 2.f * k3;
                s_yt[tid] = fmaf(hsub, k3, s_y[tid]);
            }
            __syncthreads();
            vf(s0 + hsub, s_yt);
            if (tid < HID) {
                s_y[tid] = fmaf(hsub * (1.f / 6.f), s_ks[tid] + s_f[tid], s_y[tid]);
            }
            __syncthreads();
        }

        if (rank == 0) mvw<2, HID, ACT_NONE>(lW, s_y, lb, out + (size_t)(b * T_LEN + iv + 1) * OBS);
    }

    asm volatile("barrier.cluster.arrive.aligned;" ::: "memory");
    asm volatile("barrier.cluster.wait.aligned;" ::: "memory");
}

// ---------------- launch --------------------------------------------------------
static const int SMEM_BYTES = 16
    + (3 * 64 * WID + 32 * WID) * 4            // half2 weights (4B each)
    + (T_LEN * CC + 32 * CC + NTH + 3 * WID + WID + 2 * WID + 4 * HID + 4 * 36) * 4;

extern "C" void kernel_launch(void* const* d_in, const int* in_sizes, int n_in,
                              void* d_out, int out_size) {
    const float* ts  = (const float*)d_in[0];
    const float* ys  = (const float*)d_in[1];
    const float* iW0 = (const float*)d_in[2];
    const float* ib0 = (const float*)d_in[3];
    const float* iWh = (const float*)d_in[4];
    const float* ibh = (const float*)d_in[5];
    const float* iWo = (const float*)d_in[6];
    const float* ibo = (const float*)d_in[7];
    const float* fW0 = (const float*)d_in[8];
    const float* fb0 = (const float*)d_in[9];
    const float* fWh = (const float*)d_in[10];
    const float* fbh = (const float*)d_in[11];
    const float* fWo = (const float*)d_in[12];
    const float* fbo = (const float*)d_in[13];
    const float* lW  = (const float*)d_in[14];
    const float* lb  = (const float*)d_in[15];
    float* out = (float*)d_out;

    cudaFuncSetAttribute(ncde_main, cudaFuncAttributeMaxDynamicSharedMemorySize, SMEM_BYTES);

    prep_fwo<<<132, 256>>>(fWo);
    prep_h2<<<112, 256>>>(fWh, fW0);
    ncde_main<<<128, NTH, SMEM_BYTES>>>(ts, ys, iW0, ib0, iWh, ibh, iWo, ibo,
                                        fb0, fbh, fbo, lW, lb, out);
}

// round 11
// speedup vs baseline: 3.8563x; 1.0089x over previous
#include <cuda_runtime.h>
#include <cuda_fp16.h>
#include <stdint.h>
#include <math.h>

// ---------------- problem constants ------------------------------------------
#define NTH   512
#define T_LEN 128
#define OBS   32
#define CC    33
#define HID   64
#define WID   128
#define FOUT  2112

#define ACT_NONE 0
#define ACT_RELU 1
#define ACT_SP   2

// fWo fp16, (h, channel-pair) warp-interleaved layout (R7-proven).
__device__ __align__(16) __half g_fWoH[FOUT * WID];   // 33792 uint4

// hidden-chain weights as half2, column layout (R7-proven):
// g_fWhH2[(l*64 + kp)*128 + o] = (W[l][o][2kp], W[l][o][2kp+1])
__device__ __align__(16) __half2 g_fWhH2[3 * 64 * WID];
// g_fW0H2[kp*128 + o] = (fW0[o][2kp], fW0[o][2kp+1]), kp < 32
__device__ __align__(16) __half2 g_fW0H2[32 * WID];

__global__ void prep_fwo(const float* __restrict__ fWo) {
    int idx = blockIdx.x * blockDim.x + threadIdx.x;
    if (idx >= 33792) return;
    __half hv[8];
    if (idx < 32768) {
        int l = idx & 31;
        int t = idx >> 5;
        int chI = t & 1;  t >>= 1;
        int kc = t & 15;  t >>= 4;
        int w = t & 15;
        int r = t >> 4;
        int h = r * 32 + w * 2 + (l >> 4);
        int p = l & 15;
        int c = chI ? (p + 16) : p;
#pragma unroll
        for (int j = 0; j < 8; j++)
            hv[j] = __float2half(fWo[(h * CC + c) * WID + kc * 8 + j]);
    } else {
        int i2 = idx - 32768;
        int l = i2 & 31;
        int rw = i2 >> 5;
        int w = rw & 15;
        int r = rw >> 4;
        int h = r * 32 + w * 2 + (l >> 4);
        int p = l & 15;
#pragma unroll
        for (int j = 0; j < 8; j++)
            hv[j] = __float2half(fWo[(h * CC + 32) * WID + p * 8 + j]);
    }
    ((uint4*)g_fWoH)[idx] = *(const uint4*)hv;
}

// R7-proven prep: column-major half2 packing
__global__ void prep_h2(const float* __restrict__ fWh, const float* __restrict__ fW0) {
    int idx = blockIdx.x * blockDim.x + threadIdx.x;
    if (idx < 3 * 64 * WID) {
        int o = idx & 127;
        int t = idx >> 7;
        int kp = t & 63;
        int l = t >> 6;
        const float* row = fWh + ((size_t)(l * WID + o)) * WID;
        g_fWhH2[idx] = __floats2half2_rn(row[2 * kp], row[2 * kp + 1]);
    } else if (idx < 3 * 64 * WID + 32 * WID) {
        int i2 = idx - 3 * 64 * WID;
        int o = i2 & 127;
        int kp = i2 >> 7;
        const float* row = fW0 + (size_t)o * HID;
        g_fW0H2[i2] = __floats2half2_rn(row[2 * kp], row[2 * kp + 1]);
    }
}

// ---------------- small device helpers ---------------------------------------
__device__ __forceinline__ uint32_t s2u(const void* p) {
    return (uint32_t)__cvta_generic_to_shared(p);
}
__device__ __forceinline__ void bar_init(uint32_t addr, uint32_t count) {
    asm volatile("mbarrier.init.shared.b64 [%0], %1;" :: "r"(addr), "r"(count) : "memory");
}
__device__ __forceinline__ void bar_arrive_peer(uint32_t local_bar, uint32_t peer) {
    asm volatile(
        "{\n\t.reg .b32 ra;\n\t"
        "mapa.shared::cluster.u32 ra, %0, %1;\n\t"
        "mbarrier.arrive.release.cluster.shared::cluster.b64 _, [ra];\n\t}"
        :: "r"(local_bar), "r"(peer) : "memory");
}
__device__ __forceinline__ void st_peer_f32(uint32_t local_addr, uint32_t peer, float v) {
    asm volatile(
        "{\n\t.reg .b32 ra;\n\t"
        "mapa.shared::cluster.u32 ra, %0, %1;\n\t"
        "st.shared::cluster.f32 [ra], %2;\n\t}"
        :: "r"(local_addr), "r"(peer), "f"(v) : "memory");
}
__device__ __forceinline__ void bar_wait(uint32_t addr, uint32_t parity) {
    asm volatile(
        "{\n\t.reg .pred P;\n"
        "W%=:\n\t"
        "mbarrier.try_wait.parity.acquire.cluster.shared::cta.b64 P, [%0], %1, 0x989680;\n\t"
        "@!P bra W%=;\n\t}"
        :: "r"(addr), "r"(parity) : "memory");
}
__device__ __forceinline__ uint32_t ctarank() {
    uint32_t r;
    asm("mov.u32 %0, %%cluster_ctarank;" : "=r"(r));
    return r;
}

__device__ __forceinline__ float softplus_f(float x) {
    return fmaxf(x, 0.f) + __logf(1.f + __expf(-fabsf(x)));
}
__device__ __forceinline__ float tanh_f(float x) {
    float e = __expf(-2.0f * fabsf(x));
    float t = __fdividef(1.0f - e, 1.0f + e);
    return copysignf(t, x);
}
// fp32 dot of 8 fp16 weights against 8 fp32 activations (R7-exact)
__device__ __forceinline__ float dot8(uint4 wv, float4 xa, float4 xb, float acc) {
    const __half2* hh = (const __half2*)&wv;
    float2 f0 = __half22float2(hh[0]);
    float2 f1 = __half22float2(hh[1]);
    float2 f2 = __half22float2(hh[2]);
    float2 f3 = __half22float2(hh[3]);
    acc = fmaf(f0.x, xa.x, acc); acc = fmaf(f0.y, xa.y, acc);
    acc = fmaf(f1.x, xa.z, acc); acc = fmaf(f1.y, xa.w, acc);
    acc = fmaf(f2.x, xb.x, acc); acc = fmaf(f2.y, xb.y, acc);
    acc = fmaf(f3.x, xb.z, acc); acc = fmaf(f3.y, xb.w, acc);
    return acc;
}

// R7-proven hidden layer (column-layout weights, LDS.32 weight reads),
// with x read as float4 (proven primitive: R7's fWo hb4 reads) and
// bias passed by value. FMA sequence identical to R7's layer_h2.
template <int NKP, int ACT>
__device__ __forceinline__ void layer_h2(const __half2* __restrict__ Wc,  // [NKP][128]
                                         const float* __restrict__ x,    // 2*NKP floats
                                         float biasv,                    // bias for o = tid&127
                                         float* __restrict__ outv,       // 128
                                         float* __restrict__ s_part) {
    const int tid = threadIdx.x;
    const int o = tid & 127;
    const int p = tid >> 7;          // 0..3
    constexpr int JP = NKP / 4;      // half2 per thread
    const __half2* col = Wc + JP * p * 128 + o;
    const float4* x4 = (const float4*)x + (JP / 2) * p;
    float acc = 0.f;
#pragma unroll
    for (int m = 0; m < JP / 2; m++) {
        float4 xv = x4[m];
        float2 wfa = __half22float2(col[(2 * m) * 128]);
        float2 wfb = __half22float2(col[(2 * m + 1) * 128]);
        acc = fmaf(wfa.x, xv.x, acc);
        acc = fmaf(wfa.y, xv.y, acc);
        acc = fmaf(wfb.x, xv.z, acc);
        acc = fmaf(wfb.y, xv.w, acc);
    }
    s_part[tid] = acc;
    __syncthreads();
    if (tid < 128) {
        float v = s_part[tid] + s_part[tid + 128] + s_part[tid + 256]
                + s_part[tid + 384] + biasv;
        if (ACT == ACT_RELU) v = fmaxf(v, 0.f);
        if (ACT == ACT_SP)   v = softplus_f(v);
        outv[tid] = v;
    }
    __syncthreads();
}

// full-width fp32 warp-coop matvec (cold paths: init MLP, readout)
template <int OPW, int I, int ACT>
__device__ __forceinline__ void mvw(const float* __restrict__ W,
                                    const float* __restrict__ x,
                                    const float* __restrict__ bias,
                                    float* __restrict__ outv) {
    constexpr int NJ = (I + 31) / 32;
    const int w = threadIdx.x >> 5;
    const int l = threadIdx.x & 31;
    float xr[NJ];
#pragma unroll
    for (int j = 0; j < NJ; j++) {
        int k = l + 32 * j;
        xr[j] = (k < I) ? x[k] : 0.f;
    }
    float acc[OPW];
#pragma unroll
    for (int oo = 0; oo < OPW; oo++) {
        const float* row = W + (w * OPW + oo) * I;
        float a = 0.f;
#pragma unroll
        for (int j = 0; j < NJ; j++) {
            int k = l + 32 * j;
            if (k < I) a = fmaf(row[k], xr[j], a);
        }
        acc[oo] = a;
    }
#pragma unroll
    for (int d = 16; d >= 1; d >>= 1)
#pragma unroll
        for (int oo = 0; oo < OPW; oo++)
            acc[oo] += __shfl_xor_sync(0xFFFFFFFFu, acc[oo], d);
    if (l < OPW) {
        float v = acc[l] + bias[w * OPW + l];
        if (ACT == ACT_RELU) v = fmaxf(v, 0.f);
        if (ACT == ACT_SP)   v = softplus_f(v);
        outv[w * OPW + l] = v;
    }
}

__global__ void __launch_bounds__(NTH, 1) __cluster_dims__(2, 1, 1)
ncde_main(const float* __restrict__ ts, const float* __restrict__ ys,
          const float* __restrict__ iW0, const float* __restrict__ ib0,
          const float* __restrict__ iWh, const float* __restrict__ ibh,
          const float* __restrict__ iWo, const float* __restrict__ ibo,
          const float* __restrict__ fb0g, const float* __restrict__ fbhg,
          const float* __restrict__ fbo, const float* __restrict__ lW,
          const float* __restrict__ lb, float* __restrict__ out) {
    extern __shared__ __align__(16) char smraw[];
    __half2* s_Wh = (__half2*)(smraw + 16);          // 3*64*128 half2 = 98304 B
    __half2* s_W0 = s_Wh + 3 * 64 * WID;             // 32*128 half2 = 16384 B
    float* s_tys  = (float*)(s_W0 + 32 * WID);       // 4224 floats
    float* s_fboH = s_tys + T_LEN * CC;              // 1056
    float* s_part = s_fboH + 32 * CC;                // 512
    float* s_fbh  = s_part + NTH;                    // 384
    float* s_fb0  = s_fbh + 3 * WID;                 // 128
    float* s_ha   = s_fb0 + WID;                     // 128
    float* s_hb   = s_ha + WID;                      // 128
    float* s_y    = s_hb + WID;                      // 64
    float* s_yt   = s_y + HID;                       // 64
    float* s_ks   = s_yt + HID;                      // 64
    float* s_f    = s_ks + HID;                      // 64
    float* s_xd   = s_f + HID;                       // 36
    float* s_d0   = s_xd + 36;                       // 36
    float* s_cc   = s_d0 + 36;                       // 36
    float* s_bb   = s_cc + 36;                       // 36

    const int tid = threadIdx.x;
    const int b = blockIdx.x >> 1;
    const int rank = (int)ctarank();
    const uint32_t peer = (uint32_t)(rank ^ 1);
    const int wrp = tid >> 5;
    const int lane = tid & 31;
    const int hl = tid >> 4;          // 0..31 local h row (fWo block)
    const int p16 = tid & 15;         // channel id (fWo block)

    const uint32_t barF = s2u(smraw);
    const uint32_t u_f  = s2u(s_f);

    if (tid == 0) bar_init(barF, 32);
    __syncthreads();
    asm volatile("barrier.cluster.arrive.aligned;" ::: "memory");
    asm volatile("barrier.cluster.wait.aligned;" ::: "memory");

    // --- stage fp16 hidden weights + tys + biases ------------------------------
    {
        const uint4* src = (const uint4*)g_fWhH2;
        uint4* dst = (uint4*)s_Wh;
        for (int i = tid; i < 3 * 64 * WID / 4; i += NTH) dst[i] = src[i];
        const uint4* s2 = (const uint4*)g_fW0H2;
        uint4* d2 = (uint4*)s_W0;
        for (int i = tid; i < 32 * WID / 4; i += NTH) d2[i] = s2[i];
    }
    for (int i = tid; i < T_LEN * CC; i += NTH) {
        int t = i / CC, c = i - t * CC;
        s_tys[i] = (c == 0) ? ts[t] : ys[(b * T_LEN + t) * OBS + (c - 1)];
    }
    for (int i = tid; i < 32 * CC; i += NTH) s_fboH[i] = fbo[rank * 32 * CC + i];
    if (tid < 3 * WID) s_fbh[tid] = fbhg[tid];
    if (tid < WID)     s_fb0[tid] = fb0g[tid];
    __syncthreads();

    // hoisted loop-invariant biases (registers)
    const int o127 = tid & 127;
    const float rb0  = s_fb0[o127];
    const float rbh1 = s_fbh[o127];
    const float rbh2 = s_fbh[WID + o127];
    const float rbh3 = s_fbh[2 * WID + o127];
    const float fb_a = s_fboH[hl * CC + p16];
    const float fb_b = s_fboH[hl * CC + p16 + 16];
    const float fb_c = s_fboH[hl * CC + 32];

    int phF = 0;

    // --- initial MLP (redundant in both CTAs, fp32, cold) -> y0 ----------------
    mvw<8, CC, ACT_RELU>(iW0, s_tys, ib0, s_ha);                        __syncthreads();
    mvw<8, WID, ACT_RELU>(iWh,         s_ha, ibh,           s_hb);      __syncthreads();
    mvw<8, WID, ACT_RELU>(iWh + 16384, s_hb, ibh + WID,     s_ha);      __syncthreads();
    mvw<8, WID, ACT_RELU>(iWh + 32768, s_ha, ibh + 2 * WID, s_hb);      __syncthreads();
    mvw<4, WID, ACT_NONE>(iWo, s_hb, ibo, s_y);                         __syncthreads();

    if (rank == 0) mvw<2, HID, ACT_NONE>(lW, s_y, lb, out + (size_t)(b * T_LEN) * OBS);

    // fWo pointers for this thread (R7-proven)
    const uint4* W1  = ((const uint4*)g_fWoH) + (size_t)(rank * 16 + wrp) * 1024 + lane;
    const uint4* W2p = ((const uint4*)g_fWoH) + 32768 + (size_t)(rank * 16 + wrp) * 32 + lane;
    const int hg = rank * 32 + hl;

    // --- vector field -----------------------------------------------------------
    auto vf = [&](float s, const float* __restrict__ yy) {
        if (tid < CC)
            s_xd[tid] = s_d0[tid] + 2.f * s_cc[tid] * s + 3.f * s_bb[tid] * s * s;
        // hidden chain: fp16 smem weights (R7 path), float4 x reads
        layer_h2<32, ACT_SP>(s_W0, yy, rb0, s_ha, s_part);
        layer_h2<64, ACT_SP>(s_Wh,             s_ha, rbh1, s_hb, s_part);
        layer_h2<64, ACT_SP>(s_Wh + 64 * WID,  s_hb, rbh2, s_ha, s_part);
        layer_h2<64, ACT_SP>(s_Wh + 128 * WID, s_ha, rbh3, s_hb, s_part);

        // ---- fWo (this CTA's 32 h rows): R7 channel-pair scheme, fused reduce ----
        {
            const float4* hb4 = (const float4*)s_hb;
            float z0a = 0.f, z0b = 0.f, z1a = 0.f, z1b = 0.f;
#pragma unroll
            for (int kc = 0; kc < 16; kc += 2) {
                float4 xa0 = hb4[kc * 2],     xb0 = hb4[kc * 2 + 1];
                float4 xa1 = hb4[kc * 2 + 2], xb1 = hb4[kc * 2 + 3];
                z0a = dot8(W1[kc * 64],      xa0, xb0, z0a);
                z1a = dot8(W1[kc * 64 + 32], xa0, xb0, z1a);
                z0b = dot8(W1[kc * 64 + 64], xa1, xb1, z0b);
                z1b = dot8(W1[kc * 64 + 96], xa1, xb1, z1b);
            }
            float z0 = z0a + z0b;
            float z1 = z1a + z1b;
            float z2 = dot8(*W2p, hb4[p16 * 2], hb4[p16 * 2 + 1], 0.f);

            float part = tanh_f(z0 + fb_a) * s_xd[p16];
            part = fmaf(tanh_f(z1 + fb_b), s_xd[p16 + 16], part);
            // fused butterfly: reduce part and z2 together (independent chains)
#pragma unroll
            for (int d = 1; d <= 8; d <<= 1) {
                part += __shfl_xor_sync(0xFFFFFFFFu, part, d);
                z2   += __shfl_xor_sync(0xFFFFFFFFu, z2, d);
            }
            if (p16 == 0) {
                part = fmaf(tanh_f(z2 + fb_c), s_xd[32], part);
                s_f[hg] = part;
                st_peer_f32(u_f + hg * 4, peer, part);
                bar_arrive_peer(barF, peer);
            }
            __syncthreads();
            bar_wait(barF, phF & 1); phF++;
        }
    };

    // --- interval scan + RK4 -----------------------------------------------------
    for (int iv = 0; iv < T_LEN - 1; iv++) {
        float dti = s_tys[(iv + 1) * CC] - s_tys[iv * CC];
        if (tid < CC) {
            float di = (s_tys[(iv + 1) * CC + tid] - s_tys[iv * CC + tid]) / dti;
            float d0v;
            if (iv == 0) {
                d0v = di;
            } else {
                float dtm = s_tys[iv * CC] - s_tys[(iv - 1) * CC];
                d0v = (s_tys[iv * CC + tid] - s_tys[(iv - 1) * CC + tid]) / dtm;
            }
            float d1v = di;
            s_d0[tid] = d0v;
            s_cc[tid] = (3.f * di - 2.f * d0v - d1v) / dti;
            s_bb[tid] = (d0v + d1v - 2.f * di) / (dti * dti);
        }
        __syncthreads();

        float hsub = dti * 0.25f;
#pragma unroll 1
        for (int sub = 0; sub < 4; sub++) {
            float s0 = hsub * (float)sub;
            vf(s0, s_y);
            if (tid < HID) {
                float k1 = s_f[tid];
                s_ks[tid] = k1;
                s_yt[tid] = fmaf(0.5f * hsub, k1, s_y[tid]);
            }
            __syncthreads();
            vf(s0 + 0.5f * hsub, s_yt);
            if (tid < HID) {
                float k2 = s_f[tid];
                s_ks[tid] += 2.f * k2;
                s_yt[tid] = fmaf(0.5f * hsub, k2, s_y[tid]);
            }
            __syncthreads();
            vf(s0 + 0.5f * hsub, s_yt);
            if (tid < HID) {
                float k3 = s_f[tid];
                s_ks[tid] += 2.f * k3;
                s_yt[tid] = fmaf(hsub, k3, s_y[tid]);
            }
            __syncthreads();
            vf(s0 + hsub, s_yt);
            if (tid < HID) {
                s_y[tid] = fmaf(hsub * (1.f / 6.f), s_ks[tid] + s_f[tid], s_y[tid]);
            }
            __syncthreads();
        }

        if (rank == 0) mvw<2, HID, ACT_NONE>(lW, s_y, lb, out + (size_t)(b * T_LEN + iv + 1) * OBS);
    }

    asm volatile("barrier.cluster.arrive.aligned;" ::: "memory");
    asm volatile("barrier.cluster.wait.aligned;" ::: "memory");
}

// ---------------- launch --------------------------------------------------------
static const int SMEM_BYTES = 16
    + (3 * 64 * WID + 32 * WID) * 4            // half2 weights (4B each)
    + (T_LEN * CC + 32 * CC + NTH + 3 * WID + WID + 2 * WID + 4 * HID + 4 * 36) * 4;

extern "C" void kernel_launch(void* const* d_in, const int* in_sizes, int n_in,
                              void* d_out, int out_size) {
    const float* ts  = (const float*)d_in[0];
    const float* ys  = (const float*)d_in[1];
    const float* iW0 = (const float*)d_in[2];
    const float* ib0 = (const float*)d_in[3];
    const float* iWh = (const float*)d_in[4];
    const float* ibh = (const float*)d_in[5];
    const float* iWo = (const float*)d_in[6];
    const float* ibo = (const float*)d_in[7];
    const float* fW0 = (const float*)d_in[8];
    const float* fb0 = (const float*)d_in[9];
    const float* fWh = (const float*)d_in[10];
    const float* fbh = (const float*)d_in[11];
    const float* fWo = (const float*)d_in[12];
    const float* fbo = (const float*)d_in[13];
    const float* lW  = (const float*)d_in[14];
    const float* lb  = (const float*)d_in[15];
    float* out = (float*)d_out;

    cudaFuncSetAttribute(ncde_main, cudaFuncAttributeMaxDynamicSharedMemorySize, SMEM_BYTES);

    prep_fwo<<<132, 256>>>(fWo);
    prep_h2<<<112, 256>>>(fWh, fW0);
    ncde_main<<<128, NTH, SMEM_BYTES>>>(ts, ys, iW0, ib0, iWh, ibh, iWo, ibo,
                                        fb0, fbh, fbo, lW, lb, out);
}